// round 12
// baseline (speedup 1.0000x reference)
#include <cuda_runtime.h>
#include <cuda_bf16.h>
#include <math.h>
#include <stdint.h>

#define T_STEPS 512
#define BATCH   64
#define DDIM    512
#define HDIM    512
#define G3      1536   // 3*HDIM
#define MROWS   (T_STEPS * BATCH)   // 32768
#define KCAT    1536                // 3*DDIM : [Xh | Xl | Xh]

// ---------------- static device scratch ----------------
__device__ float         g_gi[(size_t)MROWS * G3];         // 192 MB fp32 GI
__device__ uint32_t      g_hp[BATCH * HDIM];               // packed bf16 hi/lo hidden state
__device__ int           g_bar[8];                         // rec group barriers
__device__ __nv_bfloat16 g_xc[(size_t)MROWS * KCAT];       // 96 MB  A' = [Xh|Xl|Xh]
__device__ __nv_bfloat16 g_bm[(size_t)G3 * KCAT];          // 4.5 MB B'[n][k]

// ---------------- helpers ----------------
__device__ __forceinline__ uint32_t s2u(const void* p) {
    return (uint32_t)__cvta_generic_to_shared(p);
}
__device__ __forceinline__ unsigned short f2bf(float x) {
    __nv_bfloat16 b = __float2bfloat16(x);
    return *reinterpret_cast<unsigned short*>(&b);
}
__device__ __forceinline__ float bf2f(unsigned short u) {
    __nv_bfloat16 b = *reinterpret_cast<__nv_bfloat16*>(&u);
    return __bfloat162float(b);
}
__device__ __forceinline__ void ldsm_x4(uint32_t& r0, uint32_t& r1, uint32_t& r2,
                                        uint32_t& r3, uint32_t addr) {
    asm volatile("ldmatrix.sync.aligned.m8n8.x4.shared.b16 {%0,%1,%2,%3}, [%4];"
                 : "=r"(r0), "=r"(r1), "=r"(r2), "=r"(r3) : "r"(addr));
}
__device__ __forceinline__ void mma16816(float* c, const uint32_t* a, uint32_t b0, uint32_t b1) {
    asm volatile(
        "mma.sync.aligned.m16n8k16.row.col.f32.bf16.bf16.f32 "
        "{%0,%1,%2,%3}, {%4,%5,%6,%7}, {%8,%9}, {%0,%1,%2,%3};"
        : "+f"(c[0]), "+f"(c[1]), "+f"(c[2]), "+f"(c[3])
        : "r"(a[0]), "r"(a[1]), "r"(a[2]), "r"(a[3]), "r"(b0), "r"(b1));
}
__device__ __forceinline__ int ld_acquire_gpu(const int* p) {
    int v;
    asm volatile("ld.acquire.gpu.s32 %0, [%1];" : "=r"(v) : "l"(p) : "memory");
    return v;
}
__device__ __forceinline__ void red_release_gpu(int* p, int v) {
    asm volatile("red.release.gpu.global.add.s32 [%0], %1;" :: "l"(p), "r"(v) : "memory");
}
__device__ __forceinline__ void cpa16(uint32_t smem, const void* g) {
    asm volatile("cp.async.cg.shared.global [%0], [%1], 16;" :: "r"(smem), "l"(g) : "memory");
}
#define CP_COMMIT() asm volatile("cp.async.commit_group;" ::: "memory")
#define CP_WAIT0()  asm volatile("cp.async.wait_group 0;" ::: "memory")

// ---------------- init: barrier reset + pack h0 into g_hp ----------------
__global__ __launch_bounds__(1024) void gru_init_kernel(const float* __restrict__ h0) {
    const int idx = blockIdx.x * 1024 + threadIdx.x;   // grid 32 -> 32768
    if (blockIdx.x == 0 && threadIdx.x < 8) g_bar[threadIdx.x] = 0;
    float v = h0[idx];
    unsigned short hi = f2bf(v);
    unsigned short lo = f2bf(v - bf2f(hi));
    g_hp[idx] = ((uint32_t)hi << 16) | lo;
}

// ---------------- bf16 hi/lo conversion of X -> g_xc ----------------
__global__ __launch_bounds__(256) void conv_x_kernel(const float* __restrict__ X) {
    size_t idx = ((size_t)blockIdx.x * 256 + threadIdx.x) * 4;
    size_t m = idx >> 9;
    size_t k = idx & 511;
    float4 v = *(const float4*)(X + idx);
    unsigned short h0 = f2bf(v.x), h1 = f2bf(v.y), h2 = f2bf(v.z), h3 = f2bf(v.w);
    unsigned short l0 = f2bf(v.x - bf2f(h0));
    unsigned short l1 = f2bf(v.y - bf2f(h1));
    unsigned short l2 = f2bf(v.z - bf2f(h2));
    unsigned short l3 = f2bf(v.w - bf2f(h3));
    ushort4 hv = make_ushort4(h0, h1, h2, h3);
    ushort4 lv = make_ushort4(l0, l1, l2, l3);
    ushort4* row = (ushort4*)(g_xc + m * KCAT);
    row[(k) >> 2]        = hv;
    row[(512 + k) >> 2]  = lv;
    row[(1024 + k) >> 2] = hv;
}

// ---------------- Wi -> B'[n][k] bf16 (transpose + hi/lo concat) ----------------
__global__ __launch_bounds__(256) void conv_w_kernel(const float* __restrict__ Wi) {
    __shared__ float tl[32][33];
    const int tx = threadIdx.x;
    const int ty = threadIdx.y;
    const int k0 = blockIdx.x * 32;
    const int n0 = blockIdx.y * 32;
    #pragma unroll
    for (int i = 0; i < 4; ++i) {
        int kk = ty + i * 8;
        tl[kk][tx] = Wi[(size_t)(k0 + kk) * G3 + n0 + tx];
    }
    __syncthreads();
    #pragma unroll
    for (int i = 0; i < 4; ++i) {
        int n = n0 + ty + i * 8;
        float v = tl[tx][ty + i * 8];
        unsigned short hi = f2bf(v);
        unsigned short lo = f2bf(v - bf2f(hi));
        __nv_bfloat16* row = g_bm + (size_t)n * KCAT;
        *reinterpret_cast<unsigned short*>(row + k0 + tx)        = hi;
        *reinterpret_cast<unsigned short*>(row + 512 + k0 + tx)  = hi;
        *reinterpret_cast<unsigned short*>(row + 1024 + k0 + tx) = lo;
    }
}

// ---------------- Phase 1: GI = A' @ B'^T via mma.sync bf16 + cp.async staging ----------------
#define NKCH (KCAT / 32)    // 48

__global__ __launch_bounds__(256) void gi_mma_kernel(const float* __restrict__ bi) {
    __shared__ __align__(16) __nv_bfloat16 As[2][128][40];
    __shared__ __align__(16) __nv_bfloat16 Bs[2][128][40];

    const int tid  = threadIdx.x;
    const int lane = tid & 31;
    const int wid  = tid >> 5;
    const int wm   = wid & 1;
    const int wn   = wid >> 1;
    const int bx   = blockIdx.x;     // N tile (12)
    const int by   = blockIdx.y;     // M tile (256)

    const int grow = tid >> 1;
    const int gc0  = (tid & 1) * 2;
    const __nv_bfloat16* Ag = g_xc + (size_t)(by * 128 + grow) * KCAT + gc0 * 8;
    const __nv_bfloat16* Bg = g_bm + (size_t)(bx * 128 + grow) * KCAT + gc0 * 8;

    // smem destinations for this thread's staged 2x16B (A) + 2x16B (B)
    const uint32_t sa0 = s2u(&As[0][grow][gc0 * 8]);
    const uint32_t sa1 = s2u(&As[0][grow][(gc0 + 1) * 8]);
    const uint32_t sb0 = s2u(&Bs[0][grow][gc0 * 8]);
    const uint32_t sb1 = s2u(&Bs[0][grow][(gc0 + 1) * 8]);
    const uint32_t abuf = 128 * 40 * 2;   // bytes per A buffer
    const uint32_t bbuf = 128 * 40 * 2;   // bytes per B buffer

    float acc[4][4][4];
    #pragma unroll
    for (int mt = 0; mt < 4; ++mt)
        #pragma unroll
        for (int nt = 0; nt < 4; ++nt)
            #pragma unroll
            for (int i = 0; i < 4; ++i) acc[mt][nt][i] = 0.f;

    // preload chunk 0 into buf 0 (async)
    cpa16(sa0, Ag);
    cpa16(sa1, Ag + 8);
    cpa16(sb0, Bg);
    cpa16(sb1, Bg + 8);
    CP_COMMIT();
    CP_WAIT0();
    __syncthreads();

    const int lrow = lane & 15;
    const int lkof = (lane >> 4) * 8;

    #pragma unroll 1
    for (int kt = 0; kt < NKCH; ++kt) {
        const int buf = kt & 1;
        // issue async staging of chunk kt+1 into the other buffer; overlaps compute
        if (kt + 1 < NKCH) {
            const int nb = buf ^ 1;
            const __nv_bfloat16* An = Ag + (kt + 1) * 32;
            const __nv_bfloat16* Bn = Bg + (kt + 1) * 32;
            cpa16(sa0 + nb * abuf, An);
            cpa16(sa1 + nb * abuf, An + 8);
            cpa16(sb0 + nb * bbuf, Bn);
            cpa16(sb1 + nb * bbuf, Bn + 8);
            CP_COMMIT();
        }

        #pragma unroll
        for (int ks = 0; ks < 2; ++ks) {
            uint32_t a[4][4];
            uint32_t bb[2][4];
            #pragma unroll
            for (int mt = 0; mt < 4; ++mt) {
                uint32_t ad = s2u(&As[buf][wm * 64 + mt * 16 + lrow][ks * 16 + lkof]);
                ldsm_x4(a[mt][0], a[mt][1], a[mt][2], a[mt][3], ad);
            }
            #pragma unroll
            for (int bt = 0; bt < 2; ++bt) {
                uint32_t bd = s2u(&Bs[buf][wn * 32 + bt * 16 + lrow][ks * 16 + lkof]);
                ldsm_x4(bb[bt][0], bb[bt][1], bb[bt][2], bb[bt][3], bd);
            }
            #pragma unroll
            for (int mt = 0; mt < 4; ++mt)
                #pragma unroll
                for (int nt = 0; nt < 4; ++nt) {
                    const int bt = nt >> 1, od = nt & 1;
                    mma16816(acc[mt][nt], a[mt], bb[bt][od], bb[bt][od + 2]);
                }
        }

        if (kt + 1 < NKCH) {
            CP_WAIT0();
            __syncthreads();
        }
    }

    #pragma unroll
    for (int mt = 0; mt < 4; ++mt) {
        const int row = by * 128 + wm * 64 + mt * 16 + (lane >> 2);
        #pragma unroll
        for (int nt = 0; nt < 4; ++nt) {
            const int col = bx * 128 + wn * 32 + nt * 8 + (lane & 3) * 2;
            const float b0 = bi[col], b1 = bi[col + 1];
            float* p0 = g_gi + (size_t)row * G3 + col;
            float* p1 = g_gi + (size_t)(row + 8) * G3 + col;
            *(float2*)p0 = make_float2(acc[mt][nt][0] + b0, acc[mt][nt][1] + b1);
            *(float2*)p1 = make_float2(acc[mt][nt][2] + b0, acc[mt][nt][3] + b1);
        }
    }
}

// ---------------- Phase 2: persistent recurrence via mma.sync bf16 hi/lo ----------------
// 128 CTAs = 4 batch-groups (16 rows) x 32 col-CTAs (16 h-cols = 48 gate-cols).
// Fused single ki-loop: load Ah/Al/Bh/Bl fragments once, issue all 18 MMAs.
#define BSTR 520
#define REC_SMEM_BYTES (2 * 48 * BSTR * 2 + 2 * 16 * BSTR * 2 + 8 * 16 * 50 * 4)  // 158720

__global__ __launch_bounds__(256) void gru_rec_kernel(
    const float* __restrict__ h0, const float* __restrict__ Wh,
    const float* __restrict__ bhn, float* __restrict__ out)
{
    extern __shared__ char smem[];
    __nv_bfloat16* Bh = (__nv_bfloat16*)smem;            // [48][520]
    __nv_bfloat16* Bl = Bh + 48 * BSTR;                  // [48][520]
    __nv_bfloat16* Ah = Bl + 48 * BSTR;                  // [16][520]
    __nv_bfloat16* Al = Ah + 16 * BSTR;                  // [16][520]
    float*        parts = (float*)(Al + 16 * BSTR);      // [8][16][50]

    const int tid  = threadIdx.x;
    const int lane = tid & 31;
    const int ks   = tid >> 5;         // warp = k-split 0..7 (64 k per step)
    const int bg   = blockIdx.x >> 5;  // batch group 0..3 (16 rows)
    const int ic   = blockIdx.x & 31;  // col group 0..31  (16 h-cols)

    // --- one-time: Wh slice -> bf16 hi/lo, B layout [j][k], j: 0-15 r, 16-31 z, 32-47 n
    for (int q = tid; q < 48 * 512; q += 256) {
        int k = q / 48;
        int j = q - k * 48;
        int gc = (j >> 4) * 512 + ic * 16 + (j & 15);
        float v = Wh[(size_t)k * G3 + gc];
        unsigned short hi = f2bf(v);
        unsigned short lo = f2bf(v - bf2f(hi));
        *reinterpret_cast<unsigned short*>(Bh + j * BSTR + k) = hi;
        *reinterpret_cast<unsigned short*>(Bl + j * BSTR + k) = lo;
    }

    const int orow = tid >> 4;
    const int oc   = tid & 15;
    const int hcol = ic * 16 + oc;
    const int brow = bg * 16 + orow;
    const float bh = bhn[hcol];
    float hold = h0[brow * HDIM + hcol];   // owner-thread register copy of h_old

    const int lrow = lane & 15;
    const int lkof = (lane >> 4) * 8;
    const uint32_t* hp = g_hp + bg * 16 * HDIM;   // group's 16 rows, packed

    __syncthreads();

    for (int t = 0; t < T_STEPS; ++t) {
        // --- prefetch gi (DRAM latency hidden behind unpack + GEMM) ---
        const float* gp = g_gi + ((size_t)t * BATCH + brow) * G3 + hcol;
        float gr = gp[0], gz = gp[512], gn = gp[1024];

        // --- per-warp unpack of this warp's A k-slice [ks*64, ks*64+64) ---
        {
            const uint32_t* hps = hp + ks * 64;
            #pragma unroll
            for (int i = lane; i < 256; i += 32) {
                int m   = i >> 4;
                int q16 = (i & 15) * 4;
                uint4 p = *(const uint4*)&hps[m * HDIM + q16];
                uint32_t hi01 = __byte_perm(p.x, p.y, 0x7632);
                uint32_t lo01 = __byte_perm(p.x, p.y, 0x5410);
                uint32_t hi23 = __byte_perm(p.z, p.w, 0x7632);
                uint32_t lo23 = __byte_perm(p.z, p.w, 0x5410);
                *(uint2*)(Ah + m * BSTR + ks * 64 + q16) = make_uint2(hi01, hi23);
                *(uint2*)(Al + m * BSTR + ks * 64 + q16) = make_uint2(lo01, lo23);
            }
        }
        __syncwarp();

        // --- fused GEMM: per ki load Ah/Al + Bh/Bl fragments once, 18 MMAs ---
        float acc[6][4];
        #pragma unroll
        for (int nt = 0; nt < 6; ++nt)
            #pragma unroll
            for (int i = 0; i < 4; ++i) acc[nt][i] = 0.f;

        #pragma unroll
        for (int ki = 0; ki < 4; ++ki) {
            const int k0 = ks * 64 + ki * 16;
            uint32_t ah[4], al[4];
            ldsm_x4(ah[0], ah[1], ah[2], ah[3], s2u(Ah + lrow * BSTR + k0 + lkof));
            ldsm_x4(al[0], al[1], al[2], al[3], s2u(Al + lrow * BSTR + k0 + lkof));
            uint32_t bhf[3][4], blf[3][4];
            #pragma unroll
            for (int bt = 0; bt < 3; ++bt) {
                ldsm_x4(bhf[bt][0], bhf[bt][1], bhf[bt][2], bhf[bt][3],
                        s2u(Bh + (bt * 16 + lrow) * BSTR + k0 + lkof));
                ldsm_x4(blf[bt][0], blf[bt][1], blf[bt][2], blf[bt][3],
                        s2u(Bl + (bt * 16 + lrow) * BSTR + k0 + lkof));
            }
            #pragma unroll
            for (int nt = 0; nt < 6; ++nt) {
                const int bt = nt >> 1, od = nt & 1;
                mma16816(acc[nt], ah, bhf[bt][od], bhf[bt][od + 2]);
                mma16816(acc[nt], al, bhf[bt][od], bhf[bt][od + 2]);
                mma16816(acc[nt], ah, blf[bt][od], blf[bt][od + 2]);
            }
        }

        // --- stage k-split partials ---
        {
            const int pr  = lane >> 2;
            const int pcb = (lane & 3) * 2;
            #pragma unroll
            for (int nt = 0; nt < 6; ++nt) {
                const int col = nt * 8 + pcb;
                *(float2*)&parts[(ks * 16 + pr) * 50 + col]     = make_float2(acc[nt][0], acc[nt][1]);
                *(float2*)&parts[(ks * 16 + pr + 8) * 50 + col] = make_float2(acc[nt][2], acc[nt][3]);
            }
        }
        __syncthreads();

        // --- reduce 8 k-splits + gates; publish h, then arrive-early ---
        float hnew;
        {
            float sr = 0.f, sz = 0.f, sn = 0.f;
            #pragma unroll
            for (int k2 = 0; k2 < 8; ++k2) {
                const float* q = &parts[(k2 * 16 + orow) * 50];
                sr += q[oc]; sz += q[16 + oc]; sn += q[32 + oc];
            }
            float er = __expf(-(gr + sr));
            float rr = __fdividef(1.f, 1.f + er);
            float ez = __expf(-(gz + sz));
            float zz = __fdividef(1.f, 1.f + ez);
            float e2 = __expf(2.f * (gn + rr * (sn + bh)));
            float nn = 1.f - __fdividef(2.f, e2 + 1.f);   // tanh, saturates safely
            hnew = (1.f - zz) * nn + zz * hold;
            hold = hnew;
            unsigned short hi = f2bf(hnew);
            unsigned short lo = f2bf(hnew - bf2f(hi));
            g_hp[brow * HDIM + hcol] = ((uint32_t)hi << 16) | lo;
        }

        // --- CG-style group barrier: bar.sync, single release arrive, out-store
        //     in the wait window, acquire-spin, bar.sync ---
        __syncthreads();
        if (tid == 0) red_release_gpu(&g_bar[bg], 1);
        out[((size_t)t * BATCH + brow) * HDIM + hcol] = hnew;
        if (tid == 0) {
            const int target = (t + 1) * 32;
            while (ld_acquire_gpu(&g_bar[bg]) < target) { }
        }
        __syncthreads();
    }
}

// ---------------- launch (serial single-stream, proven) ----------------
extern "C" void kernel_launch(void* const* d_in, const int* in_sizes, int n_in,
                              void* d_out, int out_size)
{
    const float* x   = (const float*)d_in[0];   // [T,B,D]
    const float* h0  = (const float*)d_in[1];   // [B,H]
    const float* Wi  = (const float*)d_in[2];   // [D,3H]
    const float* Wh  = (const float*)d_in[3];   // [H,3H]
    const float* bi  = (const float*)d_in[4];   // [3H]
    const float* bhn = (const float*)d_in[5];   // [H]
    float* out = (float*)d_out;                 // [T,B,H]
    (void)in_sizes; (void)n_in; (void)out_size;

    cudaFuncSetAttribute(gru_rec_kernel,
                         cudaFuncAttributeMaxDynamicSharedMemorySize, REC_SMEM_BYTES);

    gru_init_kernel<<<32, 1024>>>(h0);

    conv_x_kernel<<<(MROWS * DDIM / 4) / 256, 256>>>(x);
    conv_w_kernel<<<dim3(16, 48), dim3(32, 8)>>>(Wi);

    dim3 g1(G3 / 128, MROWS / 128);   // (12, 256)
    gi_mma_kernel<<<g1, 256>>>(bi);

    gru_rec_kernel<<<128, 256, REC_SMEM_BYTES>>>(h0, Wh, bhn, out);
}

// round 13
// speedup vs baseline: 1.0070x; 1.0070x over previous
#include <cuda_runtime.h>
#include <cuda_bf16.h>
#include <math.h>
#include <stdint.h>

#define T_STEPS 512
#define BATCH   64
#define DDIM    512
#define HDIM    512
#define G3      1536   // 3*HDIM
#define MROWS   (T_STEPS * BATCH)   // 32768
#define KCAT    1536                // 3*DDIM : [Xh | Xl | Xh]

// ---------------- static device scratch ----------------
__device__ float         g_gi[(size_t)MROWS * G3];         // 192 MB fp32 GI
__device__ uint32_t      g_hp[BATCH * HDIM];               // packed bf16 hi/lo hidden state
__device__ int           g_bar[8];                         // rec group barriers
__device__ __nv_bfloat16 g_xc[(size_t)MROWS * KCAT];       // 96 MB  A' = [Xh|Xl|Xh]
__device__ __nv_bfloat16 g_bm[(size_t)G3 * KCAT];          // 4.5 MB B'[n][k]

// ---------------- helpers ----------------
__device__ __forceinline__ uint32_t s2u(const void* p) {
    return (uint32_t)__cvta_generic_to_shared(p);
}
__device__ __forceinline__ unsigned short f2bf(float x) {
    __nv_bfloat16 b = __float2bfloat16(x);
    return *reinterpret_cast<unsigned short*>(&b);
}
__device__ __forceinline__ float bf2f(unsigned short u) {
    __nv_bfloat16 b = *reinterpret_cast<__nv_bfloat16*>(&u);
    return __bfloat162float(b);
}
__device__ __forceinline__ void ldsm_x4(uint32_t& r0, uint32_t& r1, uint32_t& r2,
                                        uint32_t& r3, uint32_t addr) {
    asm volatile("ldmatrix.sync.aligned.m8n8.x4.shared.b16 {%0,%1,%2,%3}, [%4];"
                 : "=r"(r0), "=r"(r1), "=r"(r2), "=r"(r3) : "r"(addr));
}
__device__ __forceinline__ void mma16816(float* c, const uint32_t* a, uint32_t b0, uint32_t b1) {
    asm volatile(
        "mma.sync.aligned.m16n8k16.row.col.f32.bf16.bf16.f32 "
        "{%0,%1,%2,%3}, {%4,%5,%6,%7}, {%8,%9}, {%0,%1,%2,%3};"
        : "+f"(c[0]), "+f"(c[1]), "+f"(c[2]), "+f"(c[3])
        : "r"(a[0]), "r"(a[1]), "r"(a[2]), "r"(a[3]), "r"(b0), "r"(b1));
}
__device__ __forceinline__ int ld_acquire_gpu(const int* p) {
    int v;
    asm volatile("ld.acquire.gpu.s32 %0, [%1];" : "=r"(v) : "l"(p) : "memory");
    return v;
}
__device__ __forceinline__ void red_release_gpu(int* p, int v) {
    asm volatile("red.release.gpu.global.add.s32 [%0], %1;" :: "l"(p), "r"(v) : "memory");
}
__device__ __forceinline__ void cpa16(uint32_t smem, const void* g) {
    asm volatile("cp.async.cg.shared.global [%0], [%1], 16;" :: "r"(smem), "l"(g) : "memory");
}
#define CP_COMMIT() asm volatile("cp.async.commit_group;" ::: "memory")

// ---------------- init: barrier reset + pack h0 into g_hp ----------------
__global__ __launch_bounds__(1024) void gru_init_kernel(const float* __restrict__ h0) {
    const int idx = blockIdx.x * 1024 + threadIdx.x;   // grid 32 -> 32768
    if (blockIdx.x == 0 && threadIdx.x < 8) g_bar[threadIdx.x] = 0;
    float v = h0[idx];
    unsigned short hi = f2bf(v);
    unsigned short lo = f2bf(v - bf2f(hi));
    g_hp[idx] = ((uint32_t)hi << 16) | lo;
}

// ---------------- bf16 hi/lo conversion of X -> g_xc ----------------
__global__ __launch_bounds__(256) void conv_x_kernel(const float* __restrict__ X) {
    size_t idx = ((size_t)blockIdx.x * 256 + threadIdx.x) * 4;
    size_t m = idx >> 9;
    size_t k = idx & 511;
    float4 v = *(const float4*)(X + idx);
    unsigned short h0 = f2bf(v.x), h1 = f2bf(v.y), h2 = f2bf(v.z), h3 = f2bf(v.w);
    unsigned short l0 = f2bf(v.x - bf2f(h0));
    unsigned short l1 = f2bf(v.y - bf2f(h1));
    unsigned short l2 = f2bf(v.z - bf2f(h2));
    unsigned short l3 = f2bf(v.w - bf2f(h3));
    ushort4 hv = make_ushort4(h0, h1, h2, h3);
    ushort4 lv = make_ushort4(l0, l1, l2, l3);
    ushort4* row = (ushort4*)(g_xc + m * KCAT);
    row[(k) >> 2]        = hv;
    row[(512 + k) >> 2]  = lv;
    row[(1024 + k) >> 2] = hv;
}

// ---------------- Wi -> B'[n][k] bf16 (transpose + hi/lo concat) ----------------
__global__ __launch_bounds__(256) void conv_w_kernel(const float* __restrict__ Wi) {
    __shared__ float tl[32][33];
    const int tx = threadIdx.x;
    const int ty = threadIdx.y;
    const int k0 = blockIdx.x * 32;
    const int n0 = blockIdx.y * 32;
    #pragma unroll
    for (int i = 0; i < 4; ++i) {
        int kk = ty + i * 8;
        tl[kk][tx] = Wi[(size_t)(k0 + kk) * G3 + n0 + tx];
    }
    __syncthreads();
    #pragma unroll
    for (int i = 0; i < 4; ++i) {
        int n = n0 + ty + i * 8;
        float v = tl[tx][ty + i * 8];
        unsigned short hi = f2bf(v);
        unsigned short lo = f2bf(v - bf2f(hi));
        __nv_bfloat16* row = g_bm + (size_t)n * KCAT;
        *reinterpret_cast<unsigned short*>(row + k0 + tx)        = hi;
        *reinterpret_cast<unsigned short*>(row + 512 + k0 + tx)  = hi;
        *reinterpret_cast<unsigned short*>(row + 1024 + k0 + tx) = lo;
    }
}

// ---------------- Phase 1: GI = A' @ B'^T, 4-stage cp.async pipeline ----------------
#define NKCH (KCAT / 32)    // 48
#define NSTAGE 4
#define GI_STG_ELEMS (128 * 40)                          // elements per stage per matrix
#define GI_SMEM_BYTES (NSTAGE * GI_STG_ELEMS * 2 * 2)    // 81920 B

__global__ __launch_bounds__(256) void gi_mma_kernel(const float* __restrict__ bi) {
    extern __shared__ __align__(16) __nv_bfloat16 gism[];
    __nv_bfloat16* As = gism;                         // [4][128][40]
    __nv_bfloat16* Bs = gism + NSTAGE * GI_STG_ELEMS; // [4][128][40]

    const int tid  = threadIdx.x;
    const int lane = tid & 31;
    const int wid  = tid >> 5;
    const int wm   = wid & 1;
    const int wn   = wid >> 1;
    const int bx   = blockIdx.x;     // N tile (12)
    const int by   = blockIdx.y;     // M tile (256)

    const int grow = tid >> 1;
    const int gc0  = (tid & 1) * 2;
    const __nv_bfloat16* Ag = g_xc + (size_t)(by * 128 + grow) * KCAT + gc0 * 8;
    const __nv_bfloat16* Bg = g_bm + (size_t)(bx * 128 + grow) * KCAT + gc0 * 8;

    // this thread's staging destinations (stage 0); stride to other stages in bytes
    const uint32_t sa = s2u(As + grow * 40 + gc0 * 8);
    const uint32_t sb = s2u(Bs + grow * 40 + gc0 * 8);
    const uint32_t stg = GI_STG_ELEMS * 2;   // bytes per stage

    float acc[4][4][4];
    #pragma unroll
    for (int mt = 0; mt < 4; ++mt)
        #pragma unroll
        for (int nt = 0; nt < 4; ++nt)
            #pragma unroll
            for (int i = 0; i < 4; ++i) acc[mt][nt][i] = 0.f;

    // prologue: issue chunks 0..NSTAGE-2 (one commit group per chunk)
    #pragma unroll
    for (int s = 0; s < NSTAGE - 1; ++s) {
        const __nv_bfloat16* An = Ag + s * 32;
        const __nv_bfloat16* Bn = Bg + s * 32;
        cpa16(sa + s * stg,      An);
        cpa16(sa + s * stg + 16, An + 8);
        cpa16(sb + s * stg,      Bn);
        cpa16(sb + s * stg + 16, Bn + 8);
        CP_COMMIT();
    }

    const int lrow = lane & 15;
    const int lkof = (lane >> 4) * 8;

    #pragma unroll 1
    for (int kt = 0; kt < NKCH; ++kt) {
        const int buf = kt & (NSTAGE - 1);
        // chunk kt's copy is complete once <= NSTAGE-2 groups remain outstanding
        asm volatile("cp.async.wait_group %0;" :: "n"(NSTAGE - 2) : "memory");
        __syncthreads();

        // issue chunk kt+3 into the buffer freed at iteration kt-1
        if (kt + NSTAGE - 1 < NKCH) {
            const int nb = (kt + NSTAGE - 1) & (NSTAGE - 1);
            const __nv_bfloat16* An = Ag + (kt + NSTAGE - 1) * 32;
            const __nv_bfloat16* Bn = Bg + (kt + NSTAGE - 1) * 32;
            cpa16(sa + nb * stg,      An);
            cpa16(sa + nb * stg + 16, An + 8);
            cpa16(sb + nb * stg,      Bn);
            cpa16(sb + nb * stg + 16, Bn + 8);
            CP_COMMIT();
        }

        const __nv_bfloat16* Ab = As + buf * GI_STG_ELEMS;
        const __nv_bfloat16* Bb = Bs + buf * GI_STG_ELEMS;

        #pragma unroll
        for (int ks = 0; ks < 2; ++ks) {
            uint32_t a[4][4];
            uint32_t bb[2][4];
            #pragma unroll
            for (int mt = 0; mt < 4; ++mt) {
                uint32_t ad = s2u(Ab + (wm * 64 + mt * 16 + lrow) * 40 + ks * 16 + lkof);
                ldsm_x4(a[mt][0], a[mt][1], a[mt][2], a[mt][3], ad);
            }
            #pragma unroll
            for (int bt = 0; bt < 2; ++bt) {
                uint32_t bd = s2u(Bb + (wn * 32 + bt * 16 + lrow) * 40 + ks * 16 + lkof);
                ldsm_x4(bb[bt][0], bb[bt][1], bb[bt][2], bb[bt][3], bd);
            }
            #pragma unroll
            for (int mt = 0; mt < 4; ++mt)
                #pragma unroll
                for (int nt = 0; nt < 4; ++nt) {
                    const int bt = nt >> 1, od = nt & 1;
                    mma16816(acc[mt][nt], a[mt], bb[bt][od], bb[bt][od + 2]);
                }
        }
    }

    #pragma unroll
    for (int mt = 0; mt < 4; ++mt) {
        const int row = by * 128 + wm * 64 + mt * 16 + (lane >> 2);
        #pragma unroll
        for (int nt = 0; nt < 4; ++nt) {
            const int col = bx * 128 + wn * 32 + nt * 8 + (lane & 3) * 2;
            const float b0 = bi[col], b1 = bi[col + 1];
            float* p0 = g_gi + (size_t)row * G3 + col;
            float* p1 = g_gi + (size_t)(row + 8) * G3 + col;
            *(float2*)p0 = make_float2(acc[mt][nt][0] + b0, acc[mt][nt][1] + b1);
            *(float2*)p1 = make_float2(acc[mt][nt][2] + b0, acc[mt][nt][3] + b1);
        }
    }
}

// ---------------- Phase 2: persistent recurrence via mma.sync bf16 hi/lo ----------------
// 128 CTAs = 4 batch-groups (16 rows) x 32 col-CTAs (16 h-cols = 48 gate-cols).
// Fused single ki-loop: load Ah/Al/Bh/Bl fragments once, issue all 18 MMAs.
#define BSTR 520
#define REC_SMEM_BYTES (2 * 48 * BSTR * 2 + 2 * 16 * BSTR * 2 + 8 * 16 * 50 * 4)  // 158720

__global__ __launch_bounds__(256) void gru_rec_kernel(
    const float* __restrict__ h0, const float* __restrict__ Wh,
    const float* __restrict__ bhn, float* __restrict__ out)
{
    extern __shared__ char smem[];
    __nv_bfloat16* Bh = (__nv_bfloat16*)smem;            // [48][520]
    __nv_bfloat16* Bl = Bh + 48 * BSTR;                  // [48][520]
    __nv_bfloat16* Ah = Bl + 48 * BSTR;                  // [16][520]
    __nv_bfloat16* Al = Ah + 16 * BSTR;                  // [16][520]
    float*        parts = (float*)(Al + 16 * BSTR);      // [8][16][50]

    const int tid  = threadIdx.x;
    const int lane = tid & 31;
    const int ks   = tid >> 5;         // warp = k-split 0..7 (64 k per step)
    const int bg   = blockIdx.x >> 5;  // batch group 0..3 (16 rows)
    const int ic   = blockIdx.x & 31;  // col group 0..31  (16 h-cols)

    // --- one-time: Wh slice -> bf16 hi/lo, B layout [j][k], j: 0-15 r, 16-31 z, 32-47 n
    for (int q = tid; q < 48 * 512; q += 256) {
        int k = q / 48;
        int j = q - k * 48;
        int gc = (j >> 4) * 512 + ic * 16 + (j & 15);
        float v = Wh[(size_t)k * G3 + gc];
        unsigned short hi = f2bf(v);
        unsigned short lo = f2bf(v - bf2f(hi));
        *reinterpret_cast<unsigned short*>(Bh + j * BSTR + k) = hi;
        *reinterpret_cast<unsigned short*>(Bl + j * BSTR + k) = lo;
    }

    const int orow = tid >> 4;
    const int oc   = tid & 15;
    const int hcol = ic * 16 + oc;
    const int brow = bg * 16 + orow;
    const float bh = bhn[hcol];
    float hold = h0[brow * HDIM + hcol];   // owner-thread register copy of h_old

    const int lrow = lane & 15;
    const int lkof = (lane >> 4) * 8;
    const uint32_t* hp = g_hp + bg * 16 * HDIM;   // group's 16 rows, packed

    __syncthreads();

    for (int t = 0; t < T_STEPS; ++t) {
        // --- prefetch gi (DRAM latency hidden behind unpack + GEMM) ---
        const float* gp = g_gi + ((size_t)t * BATCH + brow) * G3 + hcol;
        float gr = gp[0], gz = gp[512], gn = gp[1024];

        // --- per-warp unpack of this warp's A k-slice [ks*64, ks*64+64) ---
        {
            const uint32_t* hps = hp + ks * 64;
            #pragma unroll
            for (int i = lane; i < 256; i += 32) {
                int m   = i >> 4;
                int q16 = (i & 15) * 4;
                uint4 p = *(const uint4*)&hps[m * HDIM + q16];
                uint32_t hi01 = __byte_perm(p.x, p.y, 0x7632);
                uint32_t lo01 = __byte_perm(p.x, p.y, 0x5410);
                uint32_t hi23 = __byte_perm(p.z, p.w, 0x7632);
                uint32_t lo23 = __byte_perm(p.z, p.w, 0x5410);
                *(uint2*)(Ah + m * BSTR + ks * 64 + q16) = make_uint2(hi01, hi23);
                *(uint2*)(Al + m * BSTR + ks * 64 + q16) = make_uint2(lo01, lo23);
            }
        }
        __syncwarp();

        // --- fused GEMM: per ki load Ah/Al + Bh/Bl fragments once, 18 MMAs ---
        float acc[6][4];
        #pragma unroll
        for (int nt = 0; nt < 6; ++nt)
            #pragma unroll
            for (int i = 0; i < 4; ++i) acc[nt][i] = 0.f;

        #pragma unroll
        for (int ki = 0; ki < 4; ++ki) {
            const int k0 = ks * 64 + ki * 16;
            uint32_t ah[4], al[4];
            ldsm_x4(ah[0], ah[1], ah[2], ah[3], s2u(Ah + lrow * BSTR + k0 + lkof));
            ldsm_x4(al[0], al[1], al[2], al[3], s2u(Al + lrow * BSTR + k0 + lkof));
            uint32_t bhf[3][4], blf[3][4];
            #pragma unroll
            for (int bt = 0; bt < 3; ++bt) {
                ldsm_x4(bhf[bt][0], bhf[bt][1], bhf[bt][2], bhf[bt][3],
                        s2u(Bh + (bt * 16 + lrow) * BSTR + k0 + lkof));
                ldsm_x4(blf[bt][0], blf[bt][1], blf[bt][2], blf[bt][3],
                        s2u(Bl + (bt * 16 + lrow) * BSTR + k0 + lkof));
            }
            #pragma unroll
            for (int nt = 0; nt < 6; ++nt) {
                const int bt = nt >> 1, od = nt & 1;
                mma16816(acc[nt], ah, bhf[bt][od], bhf[bt][od + 2]);
                mma16816(acc[nt], al, bhf[bt][od], bhf[bt][od + 2]);
                mma16816(acc[nt], ah, blf[bt][od], blf[bt][od + 2]);
            }
        }

        // --- stage k-split partials ---
        {
            const int pr  = lane >> 2;
            const int pcb = (lane & 3) * 2;
            #pragma unroll
            for (int nt = 0; nt < 6; ++nt) {
                const int col = nt * 8 + pcb;
                *(float2*)&parts[(ks * 16 + pr) * 50 + col]     = make_float2(acc[nt][0], acc[nt][1]);
                *(float2*)&parts[(ks * 16 + pr + 8) * 50 + col] = make_float2(acc[nt][2], acc[nt][3]);
            }
        }
        __syncthreads();

        // --- reduce 8 k-splits + gates; publish h, then arrive-early ---
        float hnew;
        {
            float sr = 0.f, sz = 0.f, sn = 0.f;
            #pragma unroll
            for (int k2 = 0; k2 < 8; ++k2) {
                const float* q = &parts[(k2 * 16 + orow) * 50];
                sr += q[oc]; sz += q[16 + oc]; sn += q[32 + oc];
            }
            float er = __expf(-(gr + sr));
            float rr = __fdividef(1.f, 1.f + er);
            float ez = __expf(-(gz + sz));
            float zz = __fdividef(1.f, 1.f + ez);
            float e2 = __expf(2.f * (gn + rr * (sn + bh)));
            float nn = 1.f - __fdividef(2.f, e2 + 1.f);   // tanh, saturates safely
            hnew = (1.f - zz) * nn + zz * hold;
            hold = hnew;
            unsigned short hi = f2bf(hnew);
            unsigned short lo = f2bf(hnew - bf2f(hi));
            g_hp[brow * HDIM + hcol] = ((uint32_t)hi << 16) | lo;
        }

        // --- CG-style group barrier: bar.sync, single release arrive, out-store
        //     in the wait window, acquire-spin, bar.sync ---
        __syncthreads();
        if (tid == 0) red_release_gpu(&g_bar[bg], 1);
        out[((size_t)t * BATCH + brow) * HDIM + hcol] = hnew;
        if (tid == 0) {
            const int target = (t + 1) * 32;
            while (ld_acquire_gpu(&g_bar[bg]) < target) { }
        }
        __syncthreads();
    }
}

// ---------------- launch (serial single-stream, proven) ----------------
extern "C" void kernel_launch(void* const* d_in, const int* in_sizes, int n_in,
                              void* d_out, int out_size)
{
    const float* x   = (const float*)d_in[0];   // [T,B,D]
    const float* h0  = (const float*)d_in[1];   // [B,H]
    const float* Wi  = (const float*)d_in[2];   // [D,3H]
    const float* Wh  = (const float*)d_in[3];   // [H,3H]
    const float* bi  = (const float*)d_in[4];   // [3H]
    const float* bhn = (const float*)d_in[5];   // [H]
    float* out = (float*)d_out;                 // [T,B,H]
    (void)in_sizes; (void)n_in; (void)out_size;

    cudaFuncSetAttribute(gru_rec_kernel,
                         cudaFuncAttributeMaxDynamicSharedMemorySize, REC_SMEM_BYTES);
    cudaFuncSetAttribute(gi_mma_kernel,
                         cudaFuncAttributeMaxDynamicSharedMemorySize, GI_SMEM_BYTES);

    gru_init_kernel<<<32, 1024>>>(h0);

    conv_x_kernel<<<(MROWS * DDIM / 4) / 256, 256>>>(x);
    conv_w_kernel<<<dim3(16, 48), dim3(32, 8)>>>(Wi);

    dim3 g1(G3 / 128, MROWS / 128);   // (12, 256)
    gi_mma_kernel<<<g1, 256, GI_SMEM_BYTES>>>(bi);

    gru_rec_kernel<<<128, 256, REC_SMEM_BYTES>>>(h0, Wh, bhn, out);
}

// round 14
// speedup vs baseline: 1.0333x; 1.0261x over previous
#include <cuda_runtime.h>
#include <cuda_bf16.h>
#include <math.h>
#include <stdint.h>

#define T_STEPS 512
#define BATCH   64
#define DDIM    512
#define HDIM    512
#define G3      1536   // 3*HDIM
#define MROWS   (T_STEPS * BATCH)   // 32768
#define KCAT    1536                // 3*DDIM : [Xh | Xl | Xh]

// ---------------- static device scratch ----------------
__device__ float         g_gi[(size_t)MROWS * G3];         // 192 MB fp32 GI
__device__ uint32_t      g_hp[BATCH * HDIM];               // packed bf16 hi/lo hidden state
__device__ int           g_bar[8 * 32];                    // rec group barriers, 128B apart
__device__ __nv_bfloat16 g_xc[(size_t)MROWS * KCAT];       // 96 MB  A' = [Xh|Xl|Xh]
__device__ __nv_bfloat16 g_bm[(size_t)G3 * KCAT];          // 4.5 MB B'[n][k]

// ---------------- helpers ----------------
__device__ __forceinline__ uint32_t s2u(const void* p) {
    return (uint32_t)__cvta_generic_to_shared(p);
}
__device__ __forceinline__ unsigned short f2bf(float x) {
    __nv_bfloat16 b = __float2bfloat16(x);
    return *reinterpret_cast<unsigned short*>(&b);
}
__device__ __forceinline__ float bf2f(unsigned short u) {
    __nv_bfloat16 b = *reinterpret_cast<__nv_bfloat16*>(&u);
    return __bfloat162float(b);
}
__device__ __forceinline__ void ldsm_x4(uint32_t& r0, uint32_t& r1, uint32_t& r2,
                                        uint32_t& r3, uint32_t addr) {
    asm volatile("ldmatrix.sync.aligned.m8n8.x4.shared.b16 {%0,%1,%2,%3}, [%4];"
                 : "=r"(r0), "=r"(r1), "=r"(r2), "=r"(r3) : "r"(addr));
}
__device__ __forceinline__ void mma16816(float* c, const uint32_t* a, uint32_t b0, uint32_t b1) {
    asm volatile(
        "mma.sync.aligned.m16n8k16.row.col.f32.bf16.bf16.f32 "
        "{%0,%1,%2,%3}, {%4,%5,%6,%7}, {%8,%9}, {%0,%1,%2,%3};"
        : "+f"(c[0]), "+f"(c[1]), "+f"(c[2]), "+f"(c[3])
        : "r"(a[0]), "r"(a[1]), "r"(a[2]), "r"(a[3]), "r"(b0), "r"(b1));
}
__device__ __forceinline__ int ld_acquire_gpu(const int* p) {
    int v;
    asm volatile("ld.acquire.gpu.s32 %0, [%1];" : "=r"(v) : "l"(p) : "memory");
    return v;
}
__device__ __forceinline__ void red_release_gpu(int* p, int v) {
    asm volatile("red.release.gpu.global.add.s32 [%0], %1;" :: "l"(p), "r"(v) : "memory");
}

// ---------------- init: barrier reset + pack h0 into g_hp ----------------
__global__ __launch_bounds__(1024) void gru_init_kernel(const float* __restrict__ h0) {
    const int idx = blockIdx.x * 1024 + threadIdx.x;   // grid 32 -> 32768
    if (blockIdx.x == 0 && threadIdx.x < 8 * 32) g_bar[threadIdx.x] = 0;
    float v = h0[idx];
    unsigned short hi = f2bf(v);
    unsigned short lo = f2bf(v - bf2f(hi));
    g_hp[idx] = ((uint32_t)hi << 16) | lo;
}

// ---------------- bf16 hi/lo conversion of X -> g_xc ----------------
__global__ __launch_bounds__(256) void conv_x_kernel(const float* __restrict__ X) {
    size_t idx = ((size_t)blockIdx.x * 256 + threadIdx.x) * 4;
    size_t m = idx >> 9;
    size_t k = idx & 511;
    float4 v = *(const float4*)(X + idx);
    unsigned short h0 = f2bf(v.x), h1 = f2bf(v.y), h2 = f2bf(v.z), h3 = f2bf(v.w);
    unsigned short l0 = f2bf(v.x - bf2f(h0));
    unsigned short l1 = f2bf(v.y - bf2f(h1));
    unsigned short l2 = f2bf(v.z - bf2f(h2));
    unsigned short l3 = f2bf(v.w - bf2f(h3));
    ushort4 hv = make_ushort4(h0, h1, h2, h3);
    ushort4 lv = make_ushort4(l0, l1, l2, l3);
    ushort4* row = (ushort4*)(g_xc + m * KCAT);
    row[(k) >> 2]        = hv;
    row[(512 + k) >> 2]  = lv;
    row[(1024 + k) >> 2] = hv;
}

// ---------------- Wi -> B'[n][k] bf16 (transpose + hi/lo concat) ----------------
__global__ __launch_bounds__(256) void conv_w_kernel(const float* __restrict__ Wi) {
    __shared__ float tl[32][33];
    const int tx = threadIdx.x;
    const int ty = threadIdx.y;
    const int k0 = blockIdx.x * 32;
    const int n0 = blockIdx.y * 32;
    #pragma unroll
    for (int i = 0; i < 4; ++i) {
        int kk = ty + i * 8;
        tl[kk][tx] = Wi[(size_t)(k0 + kk) * G3 + n0 + tx];
    }
    __syncthreads();
    #pragma unroll
    for (int i = 0; i < 4; ++i) {
        int n = n0 + ty + i * 8;
        float v = tl[tx][ty + i * 8];
        unsigned short hi = f2bf(v);
        unsigned short lo = f2bf(v - bf2f(hi));
        __nv_bfloat16* row = g_bm + (size_t)n * KCAT;
        *reinterpret_cast<unsigned short*>(row + k0 + tx)        = hi;
        *reinterpret_cast<unsigned short*>(row + 512 + k0 + tx)  = hi;
        *reinterpret_cast<unsigned short*>(row + 1024 + k0 + tx) = lo;
    }
}

// ---------------- Phase 1: GI = A' @ B'^T via mma.sync bf16 (R10 best variant) ----------------
#define NKCH (KCAT / 32)    // 48

__global__ __launch_bounds__(256) void gi_mma_kernel(const float* __restrict__ bi) {
    __shared__ __align__(16) __nv_bfloat16 As[2][128][40];
    __shared__ __align__(16) __nv_bfloat16 Bs[2][128][40];

    const int tid  = threadIdx.x;
    const int lane = tid & 31;
    const int wid  = tid >> 5;
    const int wm   = wid & 1;
    const int wn   = wid >> 1;
    const int bx   = blockIdx.x;     // N tile (12)
    const int by   = blockIdx.y;     // M tile (256)

    const int grow = tid >> 1;
    const int gc0  = (tid & 1) * 2;
    const __nv_bfloat16* Ag = g_xc + (size_t)(by * 128 + grow) * KCAT + gc0 * 8;
    const __nv_bfloat16* Bg = g_bm + (size_t)(bx * 128 + grow) * KCAT + gc0 * 8;

    float acc[4][4][4];
    #pragma unroll
    for (int mt = 0; mt < 4; ++mt)
        #pragma unroll
        for (int nt = 0; nt < 4; ++nt)
            #pragma unroll
            for (int i = 0; i < 4; ++i) acc[mt][nt][i] = 0.f;

    {
        uint4 a0 = *(const uint4*)(Ag);
        uint4 a1 = *(const uint4*)(Ag + 8);
        uint4 b0 = *(const uint4*)(Bg);
        uint4 b1 = *(const uint4*)(Bg + 8);
        *(uint4*)&As[0][grow][gc0 * 8]       = a0;
        *(uint4*)&As[0][grow][(gc0 + 1) * 8] = a1;
        *(uint4*)&Bs[0][grow][gc0 * 8]       = b0;
        *(uint4*)&Bs[0][grow][(gc0 + 1) * 8] = b1;
    }
    __syncthreads();

    const int lrow = lane & 15;
    const int lkof = (lane >> 4) * 8;

    #pragma unroll 1
    for (int kt = 0; kt < NKCH; ++kt) {
        const int buf = kt & 1;
        uint4 pa0, pa1, pb0, pb1;
        if (kt + 1 < NKCH) {
            const __nv_bfloat16* An = Ag + (kt + 1) * 32;
            const __nv_bfloat16* Bn = Bg + (kt + 1) * 32;
            pa0 = *(const uint4*)(An);
            pa1 = *(const uint4*)(An + 8);
            pb0 = *(const uint4*)(Bn);
            pb1 = *(const uint4*)(Bn + 8);
        }

        #pragma unroll
        for (int ks = 0; ks < 2; ++ks) {
            uint32_t a[4][4];
            uint32_t bb[2][4];
            #pragma unroll
            for (int mt = 0; mt < 4; ++mt) {
                uint32_t ad = s2u(&As[buf][wm * 64 + mt * 16 + lrow][ks * 16 + lkof]);
                ldsm_x4(a[mt][0], a[mt][1], a[mt][2], a[mt][3], ad);
            }
            #pragma unroll
            for (int bt = 0; bt < 2; ++bt) {
                uint32_t bd = s2u(&Bs[buf][wn * 32 + bt * 16 + lrow][ks * 16 + lkof]);
                ldsm_x4(bb[bt][0], bb[bt][1], bb[bt][2], bb[bt][3], bd);
            }
            #pragma unroll
            for (int mt = 0; mt < 4; ++mt)
                #pragma unroll
                for (int nt = 0; nt < 4; ++nt) {
                    const int bt = nt >> 1, od = nt & 1;
                    mma16816(acc[mt][nt], a[mt], bb[bt][od], bb[bt][od + 2]);
                }
        }

        if (kt + 1 < NKCH) {
            const int nb = buf ^ 1;
            *(uint4*)&As[nb][grow][gc0 * 8]       = pa0;
            *(uint4*)&As[nb][grow][(gc0 + 1) * 8] = pa1;
            *(uint4*)&Bs[nb][grow][gc0 * 8]       = pb0;
            *(uint4*)&Bs[nb][grow][(gc0 + 1) * 8] = pb1;
            __syncthreads();
        }
    }

    #pragma unroll
    for (int mt = 0; mt < 4; ++mt) {
        const int row = by * 128 + wm * 64 + mt * 16 + (lane >> 2);
        #pragma unroll
        for (int nt = 0; nt < 4; ++nt) {
            const int col = bx * 128 + wn * 32 + nt * 8 + (lane & 3) * 2;
            const float b0 = bi[col], b1 = bi[col + 1];
            float* p0 = g_gi + (size_t)row * G3 + col;
            float* p1 = g_gi + (size_t)(row + 8) * G3 + col;
            *(float2*)p0 = make_float2(acc[mt][nt][0] + b0, acc[mt][nt][1] + b1);
            *(float2*)p1 = make_float2(acc[mt][nt][2] + b0, acc[mt][nt][3] + b1);
        }
    }
}

// ---------------- Phase 2: persistent recurrence via mma.sync bf16 hi/lo ----------------
// 128 CTAs = 4 batch-groups (16 rows) x 32 col-CTAs (16 h-cols = 48 gate-cols).
// Fused single ki-loop; padded per-group barrier lines; streaming cache hints.
#define BSTR 520
#define REC_SMEM_BYTES (2 * 48 * BSTR * 2 + 2 * 16 * BSTR * 2 + 8 * 16 * 50 * 4)  // 158720

__global__ __launch_bounds__(256) void gru_rec_kernel(
    const float* __restrict__ h0, const float* __restrict__ Wh,
    const float* __restrict__ bhn, float* __restrict__ out)
{
    extern __shared__ char smem[];
    __nv_bfloat16* Bh = (__nv_bfloat16*)smem;            // [48][520]
    __nv_bfloat16* Bl = Bh + 48 * BSTR;                  // [48][520]
    __nv_bfloat16* Ah = Bl + 48 * BSTR;                  // [16][520]
    __nv_bfloat16* Al = Ah + 16 * BSTR;                  // [16][520]
    float*        parts = (float*)(Al + 16 * BSTR);      // [8][16][50]

    const int tid  = threadIdx.x;
    const int lane = tid & 31;
    const int ks   = tid >> 5;         // warp = k-split 0..7 (64 k per step)
    const int bg   = blockIdx.x >> 5;  // batch group 0..3 (16 rows)
    const int ic   = blockIdx.x & 31;  // col group 0..31  (16 h-cols)
    int* const bar = &g_bar[bg * 32];  // this group's private 128B barrier line

    // --- one-time: Wh slice -> bf16 hi/lo, B layout [j][k], j: 0-15 r, 16-31 z, 32-47 n
    for (int q = tid; q < 48 * 512; q += 256) {
        int k = q / 48;
        int j = q - k * 48;
        int gc = (j >> 4) * 512 + ic * 16 + (j & 15);
        float v = Wh[(size_t)k * G3 + gc];
        unsigned short hi = f2bf(v);
        unsigned short lo = f2bf(v - bf2f(hi));
        *reinterpret_cast<unsigned short*>(Bh + j * BSTR + k) = hi;
        *reinterpret_cast<unsigned short*>(Bl + j * BSTR + k) = lo;
    }

    const int orow = tid >> 4;
    const int oc   = tid & 15;
    const int hcol = ic * 16 + oc;
    const int brow = bg * 16 + orow;
    const float bh = bhn[hcol];
    float hold = h0[brow * HDIM + hcol];   // owner-thread register copy of h_old

    const int lrow = lane & 15;
    const int lkof = (lane >> 4) * 8;
    const uint32_t* hp = g_hp + bg * 16 * HDIM;   // group's 16 rows, packed

    __syncthreads();

    for (int t = 0; t < T_STEPS; ++t) {
        // --- prefetch gi (read-once stream: evict-first) ---
        const float* gp = g_gi + ((size_t)t * BATCH + brow) * G3 + hcol;
        float gr = __ldcs(gp), gz = __ldcs(gp + 512), gn = __ldcs(gp + 1024);

        // --- per-warp unpack of this warp's A k-slice [ks*64, ks*64+64) ---
        {
            const uint32_t* hps = hp + ks * 64;
            #pragma unroll
            for (int i = lane; i < 256; i += 32) {
                int m   = i >> 4;
                int q16 = (i & 15) * 4;
                uint4 p = *(const uint4*)&hps[m * HDIM + q16];
                uint32_t hi01 = __byte_perm(p.x, p.y, 0x7632);
                uint32_t lo01 = __byte_perm(p.x, p.y, 0x5410);
                uint32_t hi23 = __byte_perm(p.z, p.w, 0x7632);
                uint32_t lo23 = __byte_perm(p.z, p.w, 0x5410);
                *(uint2*)(Ah + m * BSTR + ks * 64 + q16) = make_uint2(hi01, hi23);
                *(uint2*)(Al + m * BSTR + ks * 64 + q16) = make_uint2(lo01, lo23);
            }
        }
        __syncwarp();

        // --- fused GEMM: per ki load Ah/Al + Bh/Bl fragments once, 18 MMAs ---
        float acc[6][4];
        #pragma unroll
        for (int nt = 0; nt < 6; ++nt)
            #pragma unroll
            for (int i = 0; i < 4; ++i) acc[nt][i] = 0.f;

        #pragma unroll
        for (int ki = 0; ki < 4; ++ki) {
            const int k0 = ks * 64 + ki * 16;
            uint32_t ah[4], al[4];
            ldsm_x4(ah[0], ah[1], ah[2], ah[3], s2u(Ah + lrow * BSTR + k0 + lkof));
            ldsm_x4(al[0], al[1], al[2], al[3], s2u(Al + lrow * BSTR + k0 + lkof));
            uint32_t bhf[3][4], blf[3][4];
            #pragma unroll
            for (int bt = 0; bt < 3; ++bt) {
                ldsm_x4(bhf[bt][0], bhf[bt][1], bhf[bt][2], bhf[bt][3],
                        s2u(Bh + (bt * 16 + lrow) * BSTR + k0 + lkof));
                ldsm_x4(blf[bt][0], blf[bt][1], blf[bt][2], blf[bt][3],
                        s2u(Bl + (bt * 16 + lrow) * BSTR + k0 + lkof));
            }
            #pragma unroll
            for (int nt = 0; nt < 6; ++nt) {
                const int bt = nt >> 1, od = nt & 1;
                mma16816(acc[nt], ah, bhf[bt][od], bhf[bt][od + 2]);
                mma16816(acc[nt], al, bhf[bt][od], bhf[bt][od + 2]);
                mma16816(acc[nt], ah, blf[bt][od], blf[bt][od + 2]);
            }
        }

        // --- stage k-split partials ---
        {
            const int pr  = lane >> 2;
            const int pcb = (lane & 3) * 2;
            #pragma unroll
            for (int nt = 0; nt < 6; ++nt) {
                const int col = nt * 8 + pcb;
                *(float2*)&parts[(ks * 16 + pr) * 50 + col]     = make_float2(acc[nt][0], acc[nt][1]);
                *(float2*)&parts[(ks * 16 + pr + 8) * 50 + col] = make_float2(acc[nt][2], acc[nt][3]);
            }
        }
        __syncthreads();

        // --- reduce 8 k-splits + gates; publish h, then arrive-early ---
        float hnew;
        {
            float sr = 0.f, sz = 0.f, sn = 0.f;
            #pragma unroll
            for (int k2 = 0; k2 < 8; ++k2) {
                const float* q = &parts[(k2 * 16 + orow) * 50];
                sr += q[oc]; sz += q[16 + oc]; sn += q[32 + oc];
            }
            float er = __expf(-(gr + sr));
            float rr = __fdividef(1.f, 1.f + er);
            float ez = __expf(-(gz + sz));
            float zz = __fdividef(1.f, 1.f + ez);
            float e2 = __expf(2.f * (gn + rr * (sn + bh)));
            float nn = 1.f - __fdividef(2.f, e2 + 1.f);   // tanh, saturates safely
            hnew = (1.f - zz) * nn + zz * hold;
            hold = hnew;
            unsigned short hi = f2bf(hnew);
            unsigned short lo = f2bf(hnew - bf2f(hi));
            g_hp[brow * HDIM + hcol] = ((uint32_t)hi << 16) | lo;
        }

        // --- CG-style group barrier on private 128B line; out-store (streaming)
        //     inside the wait window ---
        __syncthreads();
        if (tid == 0) red_release_gpu(bar, 1);
        __stcs(&out[((size_t)t * BATCH + brow) * HDIM + hcol], hnew);
        if (tid == 0) {
            const int target = (t + 1) * 32;
            while (ld_acquire_gpu(bar) < target) { }
        }
        __syncthreads();
    }
}

// ---------------- launch (serial single-stream, proven) ----------------
extern "C" void kernel_launch(void* const* d_in, const int* in_sizes, int n_in,
                              void* d_out, int out_size)
{
    const float* x   = (const float*)d_in[0];   // [T,B,D]
    const float* h0  = (const float*)d_in[1];   // [B,H]
    const float* Wi  = (const float*)d_in[2];   // [D,3H]
    const float* Wh  = (const float*)d_in[3];   // [H,3H]
    const float* bi  = (const float*)d_in[4];   // [3H]
    const float* bhn = (const float*)d_in[5];   // [H]
    float* out = (float*)d_out;                 // [T,B,H]
    (void)in_sizes; (void)n_in; (void)out_size;

    cudaFuncSetAttribute(gru_rec_kernel,
                         cudaFuncAttributeMaxDynamicSharedMemorySize, REC_SMEM_BYTES);

    gru_init_kernel<<<32, 1024>>>(h0);

    conv_x_kernel<<<(MROWS * DDIM / 4) / 256, 256>>>(x);
    conv_w_kernel<<<dim3(16, 48), dim3(32, 8)>>>(Wi);

    dim3 g1(G3 / 128, MROWS / 128);   // (12, 256)
    gi_mma_kernel<<<g1, 256>>>(bi);

    gru_rec_kernel<<<128, 256, REC_SMEM_BYTES>>>(h0, Wh, bhn, out);
}

// round 15
// speedup vs baseline: 1.1400x; 1.1032x over previous
#include <cuda_runtime.h>
#include <cuda_bf16.h>
#include <cuda_fp16.h>
#include <math.h>
#include <stdint.h>

#define T_STEPS 512
#define BATCH   64
#define DDIM    512
#define HDIM    512
#define G3      1536   // 3*HDIM
#define MROWS   (T_STEPS * BATCH)   // 32768
#define KCAT    1024                // 2*DDIM : [Xh | Xl]  (fp16 hi/lo)

// ---------------- static device scratch ----------------
__device__ float         g_gi[(size_t)MROWS * G3];         // 192 MB fp32 GI
__device__ uint32_t      g_hp[BATCH * HDIM];               // packed bf16 hi/lo hidden state
__device__ int           g_bar[8 * 32];                    // rec group barriers, 128B apart
__device__ __half        g_xc[(size_t)MROWS * KCAT];       // 64 MB  A' = [Xh|Xl] fp16
__device__ __half        g_bm[(size_t)G3 * KCAT];          // 3 MB   B'[n][k] = [Wh|Wh] fp16

// ---------------- helpers ----------------
__device__ __forceinline__ uint32_t s2u(const void* p) {
    return (uint32_t)__cvta_generic_to_shared(p);
}
__device__ __forceinline__ unsigned short f2bf(float x) {
    __nv_bfloat16 b = __float2bfloat16(x);
    return *reinterpret_cast<unsigned short*>(&b);
}
__device__ __forceinline__ float bf2f(unsigned short u) {
    __nv_bfloat16 b = *reinterpret_cast<__nv_bfloat16*>(&u);
    return __bfloat162float(b);
}
__device__ __forceinline__ unsigned short f2h(float x) {
    __half h = __float2half_rn(x);
    return *reinterpret_cast<unsigned short*>(&h);
}
__device__ __forceinline__ float h2f(unsigned short u) {
    __half h = *reinterpret_cast<__half*>(&u);
    return __half2float(h);
}
__device__ __forceinline__ void ldsm_x4(uint32_t& r0, uint32_t& r1, uint32_t& r2,
                                        uint32_t& r3, uint32_t addr) {
    asm volatile("ldmatrix.sync.aligned.m8n8.x4.shared.b16 {%0,%1,%2,%3}, [%4];"
                 : "=r"(r0), "=r"(r1), "=r"(r2), "=r"(r3) : "r"(addr));
}
__device__ __forceinline__ void mma16816(float* c, const uint32_t* a, uint32_t b0, uint32_t b1) {
    asm volatile(
        "mma.sync.aligned.m16n8k16.row.col.f32.bf16.bf16.f32 "
        "{%0,%1,%2,%3}, {%4,%5,%6,%7}, {%8,%9}, {%0,%1,%2,%3};"
        : "+f"(c[0]), "+f"(c[1]), "+f"(c[2]), "+f"(c[3])
        : "r"(a[0]), "r"(a[1]), "r"(a[2]), "r"(a[3]), "r"(b0), "r"(b1));
}
__device__ __forceinline__ void mma16816h(float* c, const uint32_t* a, uint32_t b0, uint32_t b1) {
    asm volatile(
        "mma.sync.aligned.m16n8k16.row.col.f32.f16.f16.f32 "
        "{%0,%1,%2,%3}, {%4,%5,%6,%7}, {%8,%9}, {%0,%1,%2,%3};"
        : "+f"(c[0]), "+f"(c[1]), "+f"(c[2]), "+f"(c[3])
        : "r"(a[0]), "r"(a[1]), "r"(a[2]), "r"(a[3]), "r"(b0), "r"(b1));
}
__device__ __forceinline__ int ld_acquire_gpu(const int* p) {
    int v;
    asm volatile("ld.acquire.gpu.s32 %0, [%1];" : "=r"(v) : "l"(p) : "memory");
    return v;
}
__device__ __forceinline__ void red_release_gpu(int* p, int v) {
    asm volatile("red.release.gpu.global.add.s32 [%0], %1;" :: "l"(p), "r"(v) : "memory");
}

// ---------------- init: barrier reset + pack h0 into g_hp ----------------
__global__ __launch_bounds__(1024) void gru_init_kernel(const float* __restrict__ h0) {
    const int idx = blockIdx.x * 1024 + threadIdx.x;   // grid 32 -> 32768
    if (blockIdx.x == 0 && threadIdx.x < 8 * 32) g_bar[threadIdx.x] = 0;
    float v = h0[idx];
    unsigned short hi = f2bf(v);
    unsigned short lo = f2bf(v - bf2f(hi));
    g_hp[idx] = ((uint32_t)hi << 16) | lo;
}

// ---------------- fp16 hi/lo conversion of X -> g_xc ----------------
__global__ __launch_bounds__(256) void conv_x_kernel(const float* __restrict__ X) {
    size_t idx = ((size_t)blockIdx.x * 256 + threadIdx.x) * 4;
    size_t m = idx >> 9;
    size_t k = idx & 511;
    float4 v = *(const float4*)(X + idx);
    unsigned short h0 = f2h(v.x), h1 = f2h(v.y), h2 = f2h(v.z), h3 = f2h(v.w);
    unsigned short l0 = f2h(v.x - h2f(h0));
    unsigned short l1 = f2h(v.y - h2f(h1));
    unsigned short l2 = f2h(v.z - h2f(h2));
    unsigned short l3 = f2h(v.w - h2f(h3));
    ushort4 hv = make_ushort4(h0, h1, h2, h3);
    ushort4 lv = make_ushort4(l0, l1, l2, l3);
    ushort4* row = (ushort4*)(g_xc + m * KCAT);
    row[(k) >> 2]       = hv;   // segment 0: Xh
    row[(512 + k) >> 2] = lv;   // segment 1: Xl
}

// ---------------- Wi -> B'[n][k] fp16 (transpose, duplicated into both segments) --------
__global__ __launch_bounds__(256) void conv_w_kernel(const float* __restrict__ Wi) {
    __shared__ float tl[32][33];
    const int tx = threadIdx.x;
    const int ty = threadIdx.y;
    const int k0 = blockIdx.x * 32;
    const int n0 = blockIdx.y * 32;
    #pragma unroll
    for (int i = 0; i < 4; ++i) {
        int kk = ty + i * 8;
        tl[kk][tx] = Wi[(size_t)(k0 + kk) * G3 + n0 + tx];
    }
    __syncthreads();
    #pragma unroll
    for (int i = 0; i < 4; ++i) {
        int n = n0 + ty + i * 8;
        float v = tl[tx][ty + i * 8];
        unsigned short hi = f2h(v);
        __half* row = g_bm + (size_t)n * KCAT;
        *reinterpret_cast<unsigned short*>(row + k0 + tx)       = hi;  // seg0 (pairs Xh)
        *reinterpret_cast<unsigned short*>(row + 512 + k0 + tx) = hi;  // seg1 (pairs Xl)
    }
}

// ---------------- Phase 1: GI = A' @ B'^T via mma.sync fp16, K=1024 ----------------
#define NKCH (KCAT / 32)    // 32

__global__ __launch_bounds__(256) void gi_mma_kernel(const float* __restrict__ bi) {
    __shared__ __align__(16) __half As[2][128][40];
    __shared__ __align__(16) __half Bs[2][128][40];

    const int tid  = threadIdx.x;
    const int lane = tid & 31;
    const int wid  = tid >> 5;
    const int wm   = wid & 1;
    const int wn   = wid >> 1;
    const int bx   = blockIdx.x;     // N tile (12)
    const int by   = blockIdx.y;     // M tile (256)

    const int grow = tid >> 1;
    const int gc0  = (tid & 1) * 2;
    const __half* Ag = g_xc + (size_t)(by * 128 + grow) * KCAT + gc0 * 8;
    const __half* Bg = g_bm + (size_t)(bx * 128 + grow) * KCAT + gc0 * 8;

    float acc[4][4][4];
    #pragma unroll
    for (int mt = 0; mt < 4; ++mt)
        #pragma unroll
        for (int nt = 0; nt < 4; ++nt)
            #pragma unroll
            for (int i = 0; i < 4; ++i) acc[mt][nt][i] = 0.f;

    {
        uint4 a0 = *(const uint4*)(Ag);
        uint4 a1 = *(const uint4*)(Ag + 8);
        uint4 b0 = *(const uint4*)(Bg);
        uint4 b1 = *(const uint4*)(Bg + 8);
        *(uint4*)&As[0][grow][gc0 * 8]       = a0;
        *(uint4*)&As[0][grow][(gc0 + 1) * 8] = a1;
        *(uint4*)&Bs[0][grow][gc0 * 8]       = b0;
        *(uint4*)&Bs[0][grow][(gc0 + 1) * 8] = b1;
    }
    __syncthreads();

    const int lrow = lane & 15;
    const int lkof = (lane >> 4) * 8;

    #pragma unroll 1
    for (int kt = 0; kt < NKCH; ++kt) {
        const int buf = kt & 1;
        uint4 pa0, pa1, pb0, pb1;
        if (kt + 1 < NKCH) {
            const __half* An = Ag + (kt + 1) * 32;
            const __half* Bn = Bg + (kt + 1) * 32;
            pa0 = *(const uint4*)(An);
            pa1 = *(const uint4*)(An + 8);
            pb0 = *(const uint4*)(Bn);
            pb1 = *(const uint4*)(Bn + 8);
        }

        #pragma unroll
        for (int ks = 0; ks < 2; ++ks) {
            uint32_t a[4][4];
            uint32_t bb[2][4];
            #pragma unroll
            for (int mt = 0; mt < 4; ++mt) {
                uint32_t ad = s2u(&As[buf][wm * 64 + mt * 16 + lrow][ks * 16 + lkof]);
                ldsm_x4(a[mt][0], a[mt][1], a[mt][2], a[mt][3], ad);
            }
            #pragma unroll
            for (int bt = 0; bt < 2; ++bt) {
                uint32_t bd = s2u(&Bs[buf][wn * 32 + bt * 16 + lrow][ks * 16 + lkof]);
                ldsm_x4(bb[bt][0], bb[bt][1], bb[bt][2], bb[bt][3], bd);
            }
            #pragma unroll
            for (int mt = 0; mt < 4; ++mt)
                #pragma unroll
                for (int nt = 0; nt < 4; ++nt) {
                    const int bt = nt >> 1, od = nt & 1;
                    mma16816h(acc[mt][nt], a[mt], bb[bt][od], bb[bt][od + 2]);
                }
        }

        if (kt + 1 < NKCH) {
            const int nb = buf ^ 1;
            *(uint4*)&As[nb][grow][gc0 * 8]       = pa0;
            *(uint4*)&As[nb][grow][(gc0 + 1) * 8] = pa1;
            *(uint4*)&Bs[nb][grow][gc0 * 8]       = pb0;
            *(uint4*)&Bs[nb][grow][(gc0 + 1) * 8] = pb1;
            __syncthreads();
        }
    }

    #pragma unroll
    for (int mt = 0; mt < 4; ++mt) {
        const int row = by * 128 + wm * 64 + mt * 16 + (lane >> 2);
        #pragma unroll
        for (int nt = 0; nt < 4; ++nt) {
            const int col = bx * 128 + wn * 32 + nt * 8 + (lane & 3) * 2;
            const float b0 = bi[col], b1 = bi[col + 1];
            float* p0 = g_gi + (size_t)row * G3 + col;
            float* p1 = g_gi + (size_t)(row + 8) * G3 + col;
            *(float2*)p0 = make_float2(acc[mt][nt][0] + b0, acc[mt][nt][1] + b1);
            *(float2*)p1 = make_float2(acc[mt][nt][2] + b0, acc[mt][nt][3] + b1);
        }
    }
}

// ---------------- Phase 2: persistent recurrence via mma.sync bf16 hi/lo ----------------
// 128 CTAs = 4 batch-groups (16 rows) x 32 col-CTAs (16 h-cols = 48 gate-cols).
// Fused single ki-loop; padded per-group barrier lines; streaming cache hints.
#define BSTR 520
#define REC_SMEM_BYTES (2 * 48 * BSTR * 2 + 2 * 16 * BSTR * 2 + 8 * 16 * 50 * 4)  // 158720

__global__ __launch_bounds__(256) void gru_rec_kernel(
    const float* __restrict__ h0, const float* __restrict__ Wh,
    const float* __restrict__ bhn, float* __restrict__ out)
{
    extern __shared__ char smem[];
    __nv_bfloat16* Bh = (__nv_bfloat16*)smem;            // [48][520]
    __nv_bfloat16* Bl = Bh + 48 * BSTR;                  // [48][520]
    __nv_bfloat16* Ah = Bl + 48 * BSTR;                  // [16][520]
    __nv_bfloat16* Al = Ah + 16 * BSTR;                  // [16][520]
    float*        parts = (float*)(Al + 16 * BSTR);      // [8][16][50]

    const int tid  = threadIdx.x;
    const int lane = tid & 31;
    const int ks   = tid >> 5;         // warp = k-split 0..7 (64 k per step)
    const int bg   = blockIdx.x >> 5;  // batch group 0..3 (16 rows)
    const int ic   = blockIdx.x & 31;  // col group 0..31  (16 h-cols)
    int* const bar = &g_bar[bg * 32];  // this group's private 128B barrier line

    // --- one-time: Wh slice -> bf16 hi/lo, B layout [j][k], j: 0-15 r, 16-31 z, 32-47 n
    for (int q = tid; q < 48 * 512; q += 256) {
        int k = q / 48;
        int j = q - k * 48;
        int gc = (j >> 4) * 512 + ic * 16 + (j & 15);
        float v = Wh[(size_t)k * G3 + gc];
        unsigned short hi = f2bf(v);
        unsigned short lo = f2bf(v - bf2f(hi));
        *reinterpret_cast<unsigned short*>(Bh + j * BSTR + k) = hi;
        *reinterpret_cast<unsigned short*>(Bl + j * BSTR + k) = lo;
    }

    const int orow = tid >> 4;
    const int oc   = tid & 15;
    const int hcol = ic * 16 + oc;
    const int brow = bg * 16 + orow;
    const float bh = bhn[hcol];
    float hold = h0[brow * HDIM + hcol];   // owner-thread register copy of h_old

    const int lrow = lane & 15;
    const int lkof = (lane >> 4) * 8;
    const uint32_t* hp = g_hp + bg * 16 * HDIM;   // group's 16 rows, packed

    __syncthreads();

    for (int t = 0; t < T_STEPS; ++t) {
        // --- prefetch gi (read-once stream: evict-first) ---
        const float* gp = g_gi + ((size_t)t * BATCH + brow) * G3 + hcol;
        float gr = __ldcs(gp), gz = __ldcs(gp + 512), gn = __ldcs(gp + 1024);

        // --- per-warp unpack of this warp's A k-slice [ks*64, ks*64+64) ---
        {
            const uint32_t* hps = hp + ks * 64;
            #pragma unroll
            for (int i = lane; i < 256; i += 32) {
                int m   = i >> 4;
                int q16 = (i & 15) * 4;
                uint4 p = *(const uint4*)&hps[m * HDIM + q16];
                uint32_t hi01 = __byte_perm(p.x, p.y, 0x7632);
                uint32_t lo01 = __byte_perm(p.x, p.y, 0x5410);
                uint32_t hi23 = __byte_perm(p.z, p.w, 0x7632);
                uint32_t lo23 = __byte_perm(p.z, p.w, 0x5410);
                *(uint2*)(Ah + m * BSTR + ks * 64 + q16) = make_uint2(hi01, hi23);
                *(uint2*)(Al + m * BSTR + ks * 64 + q16) = make_uint2(lo01, lo23);
            }
        }
        __syncwarp();

        // --- fused GEMM: per ki load Ah/Al + Bh/Bl fragments once, 18 MMAs ---
        float acc[6][4];
        #pragma unroll
        for (int nt = 0; nt < 6; ++nt)
            #pragma unroll
            for (int i = 0; i < 4; ++i) acc[nt][i] = 0.f;

        #pragma unroll
        for (int ki = 0; ki < 4; ++ki) {
            const int k0 = ks * 64 + ki * 16;
            uint32_t ah[4], al[4];
            ldsm_x4(ah[0], ah[1], ah[2], ah[3], s2u(Ah + lrow * BSTR + k0 + lkof));
            ldsm_x4(al[0], al[1], al[2], al[3], s2u(Al + lrow * BSTR + k0 + lkof));
            uint32_t bhf[3][4], blf[3][4];
            #pragma unroll
            for (int bt = 0; bt < 3; ++bt) {
                ldsm_x4(bhf[bt][0], bhf[bt][1], bhf[bt][2], bhf[bt][3],
                        s2u(Bh + (bt * 16 + lrow) * BSTR + k0 + lkof));
                ldsm_x4(blf[bt][0], blf[bt][1], blf[bt][2], blf[bt][3],
                        s2u(Bl + (bt * 16 + lrow) * BSTR + k0 + lkof));
            }
            #pragma unroll
            for (int nt = 0; nt < 6; ++nt) {
                const int bt = nt >> 1, od = nt & 1;
                mma16816(acc[nt], ah, bhf[bt][od], bhf[bt][od + 2]);
                mma16816(acc[nt], al, bhf[bt][od], bhf[bt][od + 2]);
                mma16816(acc[nt], ah, blf[bt][od], blf[bt][od + 2]);
            }
        }

        // --- stage k-split partials ---
        {
            const int pr  = lane >> 2;
            const int pcb = (lane & 3) * 2;
            #pragma unroll
            for (int nt = 0; nt < 6; ++nt) {
                const int col = nt * 8 + pcb;
                *(float2*)&parts[(ks * 16 + pr) * 50 + col]     = make_float2(acc[nt][0], acc[nt][1]);
                *(float2*)&parts[(ks * 16 + pr + 8) * 50 + col] = make_float2(acc[nt][2], acc[nt][3]);
            }
        }
        __syncthreads();

        // --- reduce 8 k-splits + gates; publish h, then arrive-early ---
        float hnew;
        {
            float sr = 0.f, sz = 0.f, sn = 0.f;
            #pragma unroll
            for (int k2 = 0; k2 < 8; ++k2) {
                const float* q = &parts[(k2 * 16 + orow) * 50];
                sr += q[oc]; sz += q[16 + oc]; sn += q[32 + oc];
            }
            float er = __expf(-(gr + sr));
            float rr = __fdividef(1.f, 1.f + er);
            float ez = __expf(-(gz + sz));
            float zz = __fdividef(1.f, 1.f + ez);
            float e2 = __expf(2.f * (gn + rr * (sn + bh)));
            float nn = 1.f - __fdividef(2.f, e2 + 1.f);   // tanh, saturates safely
            hnew = (1.f - zz) * nn + zz * hold;
            hold = hnew;
            unsigned short hi = f2bf(hnew);
            unsigned short lo = f2bf(hnew - bf2f(hi));
            g_hp[brow * HDIM + hcol] = ((uint32_t)hi << 16) | lo;
        }

        // --- CG-style group barrier on private 128B line; out-store (streaming)
        //     inside the wait window ---
        __syncthreads();
        if (tid == 0) red_release_gpu(bar, 1);
        __stcs(&out[((size_t)t * BATCH + brow) * HDIM + hcol], hnew);
        if (tid == 0) {
            const int target = (t + 1) * 32;
            while (ld_acquire_gpu(bar) < target) { }
        }
        __syncthreads();
    }
}

// ---------------- launch (serial single-stream, proven) ----------------
extern "C" void kernel_launch(void* const* d_in, const int* in_sizes, int n_in,
                              void* d_out, int out_size)
{
    const float* x   = (const float*)d_in[0];   // [T,B,D]
    const float* h0  = (const float*)d_in[1];   // [B,H]
    const float* Wi  = (const float*)d_in[2];   // [D,3H]
    const float* Wh  = (const float*)d_in[3];   // [H,3H]
    const float* bi  = (const float*)d_in[4];   // [3H]
    const float* bhn = (const float*)d_in[5];   // [H]
    float* out = (float*)d_out;                 // [T,B,H]
    (void)in_sizes; (void)n_in; (void)out_size;

    cudaFuncSetAttribute(gru_rec_kernel,
                         cudaFuncAttributeMaxDynamicSharedMemorySize, REC_SMEM_BYTES);

    gru_init_kernel<<<32, 1024>>>(h0);

    conv_x_kernel<<<(MROWS * DDIM / 4) / 256, 256>>>(x);
    conv_w_kernel<<<dim3(16, 48), dim3(32, 8)>>>(Wi);

    dim3 g1(G3 / 128, MROWS / 128);   // (12, 256)
    gi_mma_kernel<<<g1, 256>>>(bi);

    gru_rec_kernel<<<128, 256, REC_SMEM_BYTES>>>(h0, Wh, bhn, out);
}

// round 16
// speedup vs baseline: 1.2514x; 1.0977x over previous
#include <cuda_runtime.h>
#include <cuda_bf16.h>
#include <cuda_fp16.h>
#include <math.h>
#include <stdint.h>

#define T_STEPS 512
#define BATCH   64
#define DDIM    512
#define HDIM    512
#define G3      1536   // 3*HDIM
#define MROWS   (T_STEPS * BATCH)   // 32768
#define KCAT    1024                // 2*DDIM : [Xh | Xl]  (fp16 hi/lo)

// ---------------- static device scratch ----------------
__device__ float         g_gi[(size_t)MROWS * G3];         // 192 MB fp32 GI
__device__ uint32_t      g_hp[BATCH * HDIM];               // packed fp16 hi/lo hidden state
__device__ int           g_bar[8 * 32];                    // rec group barriers, 128B apart
__device__ __half        g_xc[(size_t)MROWS * KCAT];       // 64 MB  A' = [Xh|Xl] fp16
__device__ __half        g_bm[(size_t)G3 * KCAT];          // 3 MB   B'[n][k] = [Wh|Wh] fp16

// ---------------- helpers ----------------
__device__ __forceinline__ uint32_t s2u(const void* p) {
    return (uint32_t)__cvta_generic_to_shared(p);
}
__device__ __forceinline__ unsigned short f2h(float x) {
    __half h = __float2half_rn(x);
    return *reinterpret_cast<unsigned short*>(&h);
}
__device__ __forceinline__ float h2f(unsigned short u) {
    __half h = *reinterpret_cast<__half*>(&u);
    return __half2float(h);
}
__device__ __forceinline__ void ldsm_x4(uint32_t& r0, uint32_t& r1, uint32_t& r2,
                                        uint32_t& r3, uint32_t addr) {
    asm volatile("ldmatrix.sync.aligned.m8n8.x4.shared.b16 {%0,%1,%2,%3}, [%4];"
                 : "=r"(r0), "=r"(r1), "=r"(r2), "=r"(r3) : "r"(addr));
}
__device__ __forceinline__ void mma16816h(float* c, const uint32_t* a, uint32_t b0, uint32_t b1) {
    asm volatile(
        "mma.sync.aligned.m16n8k16.row.col.f32.f16.f16.f32 "
        "{%0,%1,%2,%3}, {%4,%5,%6,%7}, {%8,%9}, {%0,%1,%2,%3};"
        : "+f"(c[0]), "+f"(c[1]), "+f"(c[2]), "+f"(c[3])
        : "r"(a[0]), "r"(a[1]), "r"(a[2]), "r"(a[3]), "r"(b0), "r"(b1));
}
__device__ __forceinline__ int ld_acquire_gpu(const int* p) {
    int v;
    asm volatile("ld.acquire.gpu.s32 %0, [%1];" : "=r"(v) : "l"(p) : "memory");
    return v;
}
__device__ __forceinline__ void red_release_gpu(int* p, int v) {
    asm volatile("red.release.gpu.global.add.s32 [%0], %1;" :: "l"(p), "r"(v) : "memory");
}

// ---------------- init: barrier reset + pack h0 into g_hp (fp16 hi/lo) ----------------
__global__ __launch_bounds__(1024) void gru_init_kernel(const float* __restrict__ h0) {
    const int idx = blockIdx.x * 1024 + threadIdx.x;   // grid 32 -> 32768
    if (blockIdx.x == 0 && threadIdx.x < 8 * 32) g_bar[threadIdx.x] = 0;
    float v = h0[idx];
    unsigned short hi = f2h(v);
    unsigned short lo = f2h(v - h2f(hi));
    g_hp[idx] = ((uint32_t)hi << 16) | lo;
}

// ---------------- fp16 hi/lo conversion of X -> g_xc ----------------
__global__ __launch_bounds__(256) void conv_x_kernel(const float* __restrict__ X) {
    size_t idx = ((size_t)blockIdx.x * 256 + threadIdx.x) * 4;
    size_t m = idx >> 9;
    size_t k = idx & 511;
    float4 v = *(const float4*)(X + idx);
    unsigned short h0 = f2h(v.x), h1 = f2h(v.y), h2 = f2h(v.z), h3 = f2h(v.w);
    unsigned short l0 = f2h(v.x - h2f(h0));
    unsigned short l1 = f2h(v.y - h2f(h1));
    unsigned short l2 = f2h(v.z - h2f(h2));
    unsigned short l3 = f2h(v.w - h2f(h3));
    ushort4 hv = make_ushort4(h0, h1, h2, h3);
    ushort4 lv = make_ushort4(l0, l1, l2, l3);
    ushort4* row = (ushort4*)(g_xc + m * KCAT);
    row[(k) >> 2]       = hv;   // segment 0: Xh
    row[(512 + k) >> 2] = lv;   // segment 1: Xl
}

// ---------------- Wi -> B'[n][k] fp16 (transpose, duplicated into both segments) --------
__global__ __launch_bounds__(256) void conv_w_kernel(const float* __restrict__ Wi) {
    __shared__ float tl[32][33];
    const int tx = threadIdx.x;
    const int ty = threadIdx.y;
    const int k0 = blockIdx.x * 32;
    const int n0 = blockIdx.y * 32;
    #pragma unroll
    for (int i = 0; i < 4; ++i) {
        int kk = ty + i * 8;
        tl[kk][tx] = Wi[(size_t)(k0 + kk) * G3 + n0 + tx];
    }
    __syncthreads();
    #pragma unroll
    for (int i = 0; i < 4; ++i) {
        int n = n0 + ty + i * 8;
        float v = tl[tx][ty + i * 8];
        unsigned short hi = f2h(v);
        __half* row = g_bm + (size_t)n * KCAT;
        *reinterpret_cast<unsigned short*>(row + k0 + tx)       = hi;  // seg0 (pairs Xh)
        *reinterpret_cast<unsigned short*>(row + 512 + k0 + tx) = hi;  // seg1 (pairs Xl)
    }
}

// ---------------- Phase 1: GI = A' @ B'^T via mma.sync fp16, K=1024 (R14 proven) --------
#define NKCH (KCAT / 32)    // 32

__global__ __launch_bounds__(256) void gi_mma_kernel(const float* __restrict__ bi) {
    __shared__ __align__(16) __half As[2][128][40];
    __shared__ __align__(16) __half Bs[2][128][40];

    const int tid  = threadIdx.x;
    const int lane = tid & 31;
    const int wid  = tid >> 5;
    const int wm   = wid & 1;
    const int wn   = wid >> 1;
    const int bx   = blockIdx.x;     // N tile (12)
    const int by   = blockIdx.y;     // M tile (256)

    const int grow = tid >> 1;
    const int gc0  = (tid & 1) * 2;
    const __half* Ag = g_xc + (size_t)(by * 128 + grow) * KCAT + gc0 * 8;
    const __half* Bg = g_bm + (size_t)(bx * 128 + grow) * KCAT + gc0 * 8;

    float acc[4][4][4];
    #pragma unroll
    for (int mt = 0; mt < 4; ++mt)
        #pragma unroll
        for (int nt = 0; nt < 4; ++nt)
            #pragma unroll
            for (int i = 0; i < 4; ++i) acc[mt][nt][i] = 0.f;

    {
        uint4 a0 = *(const uint4*)(Ag);
        uint4 a1 = *(const uint4*)(Ag + 8);
        uint4 b0 = *(const uint4*)(Bg);
        uint4 b1 = *(const uint4*)(Bg + 8);
        *(uint4*)&As[0][grow][gc0 * 8]       = a0;
        *(uint4*)&As[0][grow][(gc0 + 1) * 8] = a1;
        *(uint4*)&Bs[0][grow][gc0 * 8]       = b0;
        *(uint4*)&Bs[0][grow][(gc0 + 1) * 8] = b1;
    }
    __syncthreads();

    const int lrow = lane & 15;
    const int lkof = (lane >> 4) * 8;

    #pragma unroll 1
    for (int kt = 0; kt < NKCH; ++kt) {
        const int buf = kt & 1;
        uint4 pa0, pa1, pb0, pb1;
        if (kt + 1 < NKCH) {
            const __half* An = Ag + (kt + 1) * 32;
            const __half* Bn = Bg + (kt + 1) * 32;
            pa0 = *(const uint4*)(An);
            pa1 = *(const uint4*)(An + 8);
            pb0 = *(const uint4*)(Bn);
            pb1 = *(const uint4*)(Bn + 8);
        }

        #pragma unroll
        for (int ks = 0; ks < 2; ++ks) {
            uint32_t a[4][4];
            uint32_t bb[2][4];
            #pragma unroll
            for (int mt = 0; mt < 4; ++mt) {
                uint32_t ad = s2u(&As[buf][wm * 64 + mt * 16 + lrow][ks * 16 + lkof]);
                ldsm_x4(a[mt][0], a[mt][1], a[mt][2], a[mt][3], ad);
            }
            #pragma unroll
            for (int bt = 0; bt < 2; ++bt) {
                uint32_t bd = s2u(&Bs[buf][wn * 32 + bt * 16 + lrow][ks * 16 + lkof]);
                ldsm_x4(bb[bt][0], bb[bt][1], bb[bt][2], bb[bt][3], bd);
            }
            #pragma unroll
            for (int mt = 0; mt < 4; ++mt)
                #pragma unroll
                for (int nt = 0; nt < 4; ++nt) {
                    const int bt = nt >> 1, od = nt & 1;
                    mma16816h(acc[mt][nt], a[mt], bb[bt][od], bb[bt][od + 2]);
                }
        }

        if (kt + 1 < NKCH) {
            const int nb = buf ^ 1;
            *(uint4*)&As[nb][grow][gc0 * 8]       = pa0;
            *(uint4*)&As[nb][grow][(gc0 + 1) * 8] = pa1;
            *(uint4*)&Bs[nb][grow][gc0 * 8]       = pb0;
            *(uint4*)&Bs[nb][grow][(gc0 + 1) * 8] = pb1;
            __syncthreads();
        }
    }

    #pragma unroll
    for (int mt = 0; mt < 4; ++mt) {
        const int row = by * 128 + wm * 64 + mt * 16 + (lane >> 2);
        #pragma unroll
        for (int nt = 0; nt < 4; ++nt) {
            const int col = bx * 128 + wn * 32 + nt * 8 + (lane & 3) * 2;
            const float b0 = bi[col], b1 = bi[col + 1];
            float* p0 = g_gi + (size_t)row * G3 + col;
            float* p1 = g_gi + (size_t)(row + 8) * G3 + col;
            *(float2*)p0 = make_float2(acc[mt][nt][0] + b0, acc[mt][nt][1] + b1);
            *(float2*)p1 = make_float2(acc[mt][nt][2] + b0, acc[mt][nt][3] + b1);
        }
    }
}

// ---------------- Phase 2: persistent recurrence via mma.sync fp16 2-term ----------------
// 128 CTAs = 4 batch-groups (16 rows) x 32 col-CTAs (16 h-cols = 48 gate-cols).
// gh = (hh + hl) @ Wh_fp16 : h exact as fp16 hi/lo pair, Wh single-rounded.
// 12 MMAs + 5 ldsm per ki (was 18 + 8 with bf16 3-term).
#define BSTR 520
#define REC_SMEM_BYTES ((48 * BSTR + 2 * 16 * BSTR) * 2 + 8 * 16 * 50 * 4)  // 108800

__global__ __launch_bounds__(256) void gru_rec_kernel(
    const float* __restrict__ h0, const float* __restrict__ Wh,
    const float* __restrict__ bhn, float* __restrict__ out)
{
    extern __shared__ char smem[];
    __half* Bw    = (__half*)smem;                  // [48][520] fp16 Wh
    __half* Ah    = Bw + 48 * BSTR;                 // [16][520]
    __half* Al    = Ah + 16 * BSTR;                 // [16][520]
    float*  parts = (float*)(Al + 16 * BSTR);       // [8][16][50]

    const int tid  = threadIdx.x;
    const int lane = tid & 31;
    const int ks   = tid >> 5;         // warp = k-split 0..7 (64 k per step)
    const int bg   = blockIdx.x >> 5;  // batch group 0..3 (16 rows)
    const int ic   = blockIdx.x & 31;  // col group 0..31  (16 h-cols)
    int* const bar = &g_bar[bg * 32];  // this group's private 128B barrier line

    // --- one-time: Wh slice -> fp16, B layout [j][k], j: 0-15 r, 16-31 z, 32-47 n
    for (int q = tid; q < 48 * 512; q += 256) {
        int k = q / 48;
        int j = q - k * 48;
        int gc = (j >> 4) * 512 + ic * 16 + (j & 15);
        float v = Wh[(size_t)k * G3 + gc];
        *reinterpret_cast<unsigned short*>(Bw + j * BSTR + k) = f2h(v);
    }

    const int orow = tid >> 4;
    const int oc   = tid & 15;
    const int hcol = ic * 16 + oc;
    const int brow = bg * 16 + orow;
    const float bh = bhn[hcol];
    float hold = h0[brow * HDIM + hcol];   // owner-thread register copy of h_old

    const int lrow = lane & 15;
    const int lkof = (lane >> 4) * 8;
    const uint32_t* hp = g_hp + bg * 16 * HDIM;   // group's 16 rows, packed fp16 hi/lo

    __syncthreads();

    for (int t = 0; t < T_STEPS; ++t) {
        // --- prefetch gi (read-once stream: evict-first) ---
        const float* gp = g_gi + ((size_t)t * BATCH + brow) * G3 + hcol;
        float gr = __ldcs(gp), gz = __ldcs(gp + 512), gn = __ldcs(gp + 1024);

        // --- per-warp unpack of this warp's A k-slice [ks*64, ks*64+64) ---
        {
            const uint32_t* hps = hp + ks * 64;
            #pragma unroll
            for (int i = lane; i < 256; i += 32) {
                int m   = i >> 4;
                int q16 = (i & 15) * 4;
                uint4 p = *(const uint4*)&hps[m * HDIM + q16];
                uint32_t hi01 = __byte_perm(p.x, p.y, 0x7632);
                uint32_t lo01 = __byte_perm(p.x, p.y, 0x5410);
                uint32_t hi23 = __byte_perm(p.z, p.w, 0x7632);
                uint32_t lo23 = __byte_perm(p.z, p.w, 0x5410);
                *(uint2*)(Ah + m * BSTR + ks * 64 + q16) = make_uint2(hi01, hi23);
                *(uint2*)(Al + m * BSTR + ks * 64 + q16) = make_uint2(lo01, lo23);
            }
        }
        __syncwarp();

        // --- fused GEMM: per ki load Ah/Al + Bw fragments once, 12 MMAs ---
        //     gh = Ah*Bw + Al*Bw  (fp32 accumulate)
        float acc[6][4];
        #pragma unroll
        for (int nt = 0; nt < 6; ++nt)
            #pragma unroll
            for (int i = 0; i < 4; ++i) acc[nt][i] = 0.f;

        #pragma unroll
        for (int ki = 0; ki < 4; ++ki) {
            const int k0 = ks * 64 + ki * 16;
            uint32_t ah[4], al[4];
            ldsm_x4(ah[0], ah[1], ah[2], ah[3], s2u(Ah + lrow * BSTR + k0 + lkof));
            ldsm_x4(al[0], al[1], al[2], al[3], s2u(Al + lrow * BSTR + k0 + lkof));
            uint32_t bwf[3][4];
            #pragma unroll
            for (int bt = 0; bt < 3; ++bt)
                ldsm_x4(bwf[bt][0], bwf[bt][1], bwf[bt][2], bwf[bt][3],
                        s2u(Bw + (bt * 16 + lrow) * BSTR + k0 + lkof));
            #pragma unroll
            for (int nt = 0; nt < 6; ++nt) {
                const int bt = nt >> 1, od = nt & 1;
                mma16816h(acc[nt], ah, bwf[bt][od], bwf[bt][od + 2]);
                mma16816h(acc[nt], al, bwf[bt][od], bwf[bt][od + 2]);
            }
        }

        // --- stage k-split partials ---
        {
            const int pr  = lane >> 2;
            const int pcb = (lane & 3) * 2;
            #pragma unroll
            for (int nt = 0; nt < 6; ++nt) {
                const int col = nt * 8 + pcb;
                *(float2*)&parts[(ks * 16 + pr) * 50 + col]     = make_float2(acc[nt][0], acc[nt][1]);
                *(float2*)&parts[(ks * 16 + pr + 8) * 50 + col] = make_float2(acc[nt][2], acc[nt][3]);
            }
        }
        __syncthreads();

        // --- reduce 8 k-splits + gates; publish h (fp16 hi/lo), then arrive ---
        float hnew;
        {
            float sr = 0.f, sz = 0.f, sn = 0.f;
            #pragma unroll
            for (int k2 = 0; k2 < 8; ++k2) {
                const float* q = &parts[(k2 * 16 + orow) * 50];
                sr += q[oc]; sz += q[16 + oc]; sn += q[32 + oc];
            }
            float er = __expf(-(gr + sr));
            float rr = __fdividef(1.f, 1.f + er);
            float ez = __expf(-(gz + sz));
            float zz = __fdividef(1.f, 1.f + ez);
            float e2 = __expf(2.f * (gn + rr * (sn + bh)));
            float nn = 1.f - __fdividef(2.f, e2 + 1.f);   // tanh, saturates safely
            hnew = (1.f - zz) * nn + zz * hold;
            hold = hnew;
            unsigned short hi = f2h(hnew);
            unsigned short lo = f2h(hnew - h2f(hi));
            g_hp[brow * HDIM + hcol] = ((uint32_t)hi << 16) | lo;
        }

        // --- CG-style group barrier on private 128B line; out-store (streaming)
        //     inside the wait window ---
        __syncthreads();
        if (tid == 0) red_release_gpu(bar, 1);
        __stcs(&out[((size_t)t * BATCH + brow) * HDIM + hcol], hnew);
        if (tid == 0) {
            const int target = (t + 1) * 32;
            while (ld_acquire_gpu(bar) < target) { }
        }
        __syncthreads();
    }
}

// ---------------- launch (serial single-stream, proven) ----------------
extern "C" void kernel_launch(void* const* d_in, const int* in_sizes, int n_in,
                              void* d_out, int out_size)
{
    const float* x   = (const float*)d_in[0];   // [T,B,D]
    const float* h0  = (const float*)d_in[1];   // [B,H]
    const float* Wi  = (const float*)d_in[2];   // [D,3H]
    const float* Wh  = (const float*)d_in[3];   // [H,3H]
    const float* bi  = (const float*)d_in[4];   // [3H]
    const float* bhn = (const float*)d_in[5];   // [H]
    float* out = (float*)d_out;                 // [T,B,H]
    (void)in_sizes; (void)n_in; (void)out_size;

    cudaFuncSetAttribute(gru_rec_kernel,
                         cudaFuncAttributeMaxDynamicSharedMemorySize, REC_SMEM_BYTES);

    gru_init_kernel<<<32, 1024>>>(h0);

    conv_x_kernel<<<(MROWS * DDIM / 4) / 256, 256>>>(x);
    conv_w_kernel<<<dim3(16, 48), dim3(32, 8)>>>(Wi);

    dim3 g1(G3 / 128, MROWS / 128);   // (12, 256)
    gi_mma_kernel<<<g1, 256>>>(bi);

    gru_rec_kernel<<<128, 256, REC_SMEM_BYTES>>>(h0, Wh, bhn, out);
}

// round 17
// speedup vs baseline: 1.4177x; 1.1330x over previous
#include <cuda_runtime.h>
#include <cuda_bf16.h>
#include <cuda_fp16.h>
#include <math.h>
#include <stdint.h>

#define T_STEPS 512
#define BATCH   64
#define DDIM    512
#define HDIM    512
#define G3      1536   // 3*HDIM
#define MROWS   (T_STEPS * BATCH)   // 32768
#define KCAT    512                 // single fp16 X segment

// ---------------- static device scratch ----------------
__device__ float         g_gi[(size_t)MROWS * G3];         // 192 MB fp32 GI
__device__ uint32_t      g_hp[BATCH * HDIM];               // packed fp16 hi/lo hidden state
__device__ int           g_bar[8 * 32];                    // rec group barriers, 128B apart
__device__ __half        g_xc[(size_t)MROWS * KCAT];       // 32 MB  A' = Xh fp16
__device__ __half        g_bm[(size_t)G3 * KCAT];          // 1.5 MB B'[n][k] = Wh fp16

// ---------------- helpers ----------------
__device__ __forceinline__ uint32_t s2u(const void* p) {
    return (uint32_t)__cvta_generic_to_shared(p);
}
__device__ __forceinline__ unsigned short f2h(float x) {
    __half h = __float2half_rn(x);
    return *reinterpret_cast<unsigned short*>(&h);
}
__device__ __forceinline__ float h2f(unsigned short u) {
    __half h = *reinterpret_cast<__half*>(&u);
    return __half2float(h);
}
__device__ __forceinline__ void ldsm_x4(uint32_t& r0, uint32_t& r1, uint32_t& r2,
                                        uint32_t& r3, uint32_t addr) {
    asm volatile("ldmatrix.sync.aligned.m8n8.x4.shared.b16 {%0,%1,%2,%3}, [%4];"
                 : "=r"(r0), "=r"(r1), "=r"(r2), "=r"(r3) : "r"(addr));
}
__device__ __forceinline__ void mma16816h(float* c, const uint32_t* a, uint32_t b0, uint32_t b1) {
    asm volatile(
        "mma.sync.aligned.m16n8k16.row.col.f32.f16.f16.f32 "
        "{%0,%1,%2,%3}, {%4,%5,%6,%7}, {%8,%9}, {%0,%1,%2,%3};"
        : "+f"(c[0]), "+f"(c[1]), "+f"(c[2]), "+f"(c[3])
        : "r"(a[0]), "r"(a[1]), "r"(a[2]), "r"(a[3]), "r"(b0), "r"(b1));
}
__device__ __forceinline__ int ld_acquire_gpu(const int* p) {
    int v;
    asm volatile("ld.acquire.gpu.s32 %0, [%1];" : "=r"(v) : "l"(p) : "memory");
    return v;
}
__device__ __forceinline__ void red_release_gpu(int* p, int v) {
    asm volatile("red.release.gpu.global.add.s32 [%0], %1;" :: "l"(p), "r"(v) : "memory");
}

// ---------------- init: barrier reset + pack h0 into g_hp (fp16 hi/lo) ----------------
__global__ __launch_bounds__(1024) void gru_init_kernel(const float* __restrict__ h0) {
    const int idx = blockIdx.x * 1024 + threadIdx.x;   // grid 32 -> 32768
    if (blockIdx.x == 0 && threadIdx.x < 8 * 32) g_bar[threadIdx.x] = 0;
    float v = h0[idx];
    unsigned short hi = f2h(v);
    unsigned short lo = f2h(v - h2f(hi));
    g_hp[idx] = ((uint32_t)hi << 16) | lo;
}

// ---------------- fp16 conversion of X -> g_xc (single segment) ----------------
__global__ __launch_bounds__(256) void conv_x_kernel(const float* __restrict__ X) {
    size_t idx = ((size_t)blockIdx.x * 256 + threadIdx.x) * 4;
    float4 v = *(const float4*)(X + idx);
    ushort4 hv = make_ushort4(f2h(v.x), f2h(v.y), f2h(v.z), f2h(v.w));
    *((ushort4*)g_xc + (idx >> 2)) = hv;   // same [m][k] layout, contiguous
}

// ---------------- Wi -> B'[n][k] fp16 (transpose, single segment) ----------------
__global__ __launch_bounds__(256) void conv_w_kernel(const float* __restrict__ Wi) {
    __shared__ float tl[32][33];
    const int tx = threadIdx.x;
    const int ty = threadIdx.y;
    const int k0 = blockIdx.x * 32;
    const int n0 = blockIdx.y * 32;
    #pragma unroll
    for (int i = 0; i < 4; ++i) {
        int kk = ty + i * 8;
        tl[kk][tx] = Wi[(size_t)(k0 + kk) * G3 + n0 + tx];
    }
    __syncthreads();
    #pragma unroll
    for (int i = 0; i < 4; ++i) {
        int n = n0 + ty + i * 8;
        float v = tl[tx][ty + i * 8];
        *reinterpret_cast<unsigned short*>(g_bm + (size_t)n * KCAT + k0 + tx) = f2h(v);
    }
}

// ---------------- Phase 1: GI = Xh @ Wh^T via mma.sync fp16, K=512 ----------------
#define NKCH (KCAT / 32)    // 16

__global__ __launch_bounds__(256) void gi_mma_kernel(const float* __restrict__ bi) {
    __shared__ __align__(16) __half As[2][128][40];
    __shared__ __align__(16) __half Bs[2][128][40];

    const int tid  = threadIdx.x;
    const int lane = tid & 31;
    const int wid  = tid >> 5;
    const int wm   = wid & 1;
    const int wn   = wid >> 1;
    const int bx   = blockIdx.x;     // N tile (12)
    const int by   = blockIdx.y;     // M tile (256)

    const int grow = tid >> 1;
    const int gc0  = (tid & 1) * 2;
    const __half* Ag = g_xc + (size_t)(by * 128 + grow) * KCAT + gc0 * 8;
    const __half* Bg = g_bm + (size_t)(bx * 128 + grow) * KCAT + gc0 * 8;

    float acc[4][4][4];
    #pragma unroll
    for (int mt = 0; mt < 4; ++mt)
        #pragma unroll
        for (int nt = 0; nt < 4; ++nt)
            #pragma unroll
            for (int i = 0; i < 4; ++i) acc[mt][nt][i] = 0.f;

    {
        uint4 a0 = *(const uint4*)(Ag);
        uint4 a1 = *(const uint4*)(Ag + 8);
        uint4 b0 = *(const uint4*)(Bg);
        uint4 b1 = *(const uint4*)(Bg + 8);
        *(uint4*)&As[0][grow][gc0 * 8]       = a0;
        *(uint4*)&As[0][grow][(gc0 + 1) * 8] = a1;
        *(uint4*)&Bs[0][grow][gc0 * 8]       = b0;
        *(uint4*)&Bs[0][grow][(gc0 + 1) * 8] = b1;
    }
    __syncthreads();

    const int lrow = lane & 15;
    const int lkof = (lane >> 4) * 8;

    #pragma unroll 1
    for (int kt = 0; kt < NKCH; ++kt) {
        const int buf = kt & 1;
        uint4 pa0, pa1, pb0, pb1;
        if (kt + 1 < NKCH) {
            const __half* An = Ag + (kt + 1) * 32;
            const __half* Bn = Bg + (kt + 1) * 32;
            pa0 = *(const uint4*)(An);
            pa1 = *(const uint4*)(An + 8);
            pb0 = *(const uint4*)(Bn);
            pb1 = *(const uint4*)(Bn + 8);
        }

        #pragma unroll
        for (int ks = 0; ks < 2; ++ks) {
            uint32_t a[4][4];
            uint32_t bb[2][4];
            #pragma unroll
            for (int mt = 0; mt < 4; ++mt) {
                uint32_t ad = s2u(&As[buf][wm * 64 + mt * 16 + lrow][ks * 16 + lkof]);
                ldsm_x4(a[mt][0], a[mt][1], a[mt][2], a[mt][3], ad);
            }
            #pragma unroll
            for (int bt = 0; bt < 2; ++bt) {
                uint32_t bd = s2u(&Bs[buf][wn * 32 + bt * 16 + lrow][ks * 16 + lkof]);
                ldsm_x4(bb[bt][0], bb[bt][1], bb[bt][2], bb[bt][3], bd);
            }
            #pragma unroll
            for (int mt = 0; mt < 4; ++mt)
                #pragma unroll
                for (int nt = 0; nt < 4; ++nt) {
                    const int bt = nt >> 1, od = nt & 1;
                    mma16816h(acc[mt][nt], a[mt], bb[bt][od], bb[bt][od + 2]);
                }
        }

        if (kt + 1 < NKCH) {
            const int nb = buf ^ 1;
            *(uint4*)&As[nb][grow][gc0 * 8]       = pa0;
            *(uint4*)&As[nb][grow][(gc0 + 1) * 8] = pa1;
            *(uint4*)&Bs[nb][grow][gc0 * 8]       = pb0;
            *(uint4*)&Bs[nb][grow][(gc0 + 1) * 8] = pb1;
            __syncthreads();
        }
    }

    #pragma unroll
    for (int mt = 0; mt < 4; ++mt) {
        const int row = by * 128 + wm * 64 + mt * 16 + (lane >> 2);
        #pragma unroll
        for (int nt = 0; nt < 4; ++nt) {
            const int col = bx * 128 + wn * 32 + nt * 8 + (lane & 3) * 2;
            const float b0 = bi[col], b1 = bi[col + 1];
            float* p0 = g_gi + (size_t)row * G3 + col;
            float* p1 = g_gi + (size_t)(row + 8) * G3 + col;
            *(float2*)p0 = make_float2(acc[mt][nt][0] + b0, acc[mt][nt][1] + b1);
            *(float2*)p1 = make_float2(acc[mt][nt][2] + b0, acc[mt][nt][3] + b1);
        }
    }
}

// ---------------- Phase 2: persistent recurrence via mma.sync fp16 2-term ----------------
// 128 CTAs = 4 batch-groups (16 rows) x 32 col-CTAs (16 h-cols = 48 gate-cols).
// gh = (hh + hl) @ Wh_fp16 : h exact as fp16 hi/lo pair, Wh single-rounded.
#define BSTR 520
#define REC_SMEM_BYTES ((48 * BSTR + 2 * 16 * BSTR) * 2 + 8 * 16 * 50 * 4)  // 108800

__global__ __launch_bounds__(256) void gru_rec_kernel(
    const float* __restrict__ h0, const float* __restrict__ Wh,
    const float* __restrict__ bhn, float* __restrict__ out)
{
    extern __shared__ char smem[];
    __half* Bw    = (__half*)smem;                  // [48][520] fp16 Wh
    __half* Ah    = Bw + 48 * BSTR;                 // [16][520]
    __half* Al    = Ah + 16 * BSTR;                 // [16][520]
    float*  parts = (float*)(Al + 16 * BSTR);       // [8][16][50]

    const int tid  = threadIdx.x;
    const int lane = tid & 31;
    const int ks   = tid >> 5;         // warp = k-split 0..7 (64 k per step)
    const int bg   = blockIdx.x >> 5;  // batch group 0..3 (16 rows)
    const int ic   = blockIdx.x & 31;  // col group 0..31  (16 h-cols)
    int* const bar = &g_bar[bg * 32];  // this group's private 128B barrier line

    // --- one-time: Wh slice -> fp16, B layout [j][k], j: 0-15 r, 16-31 z, 32-47 n
    for (int q = tid; q < 48 * 512; q += 256) {
        int k = q / 48;
        int j = q - k * 48;
        int gc = (j >> 4) * 512 + ic * 16 + (j & 15);
        float v = Wh[(size_t)k * G3 + gc];
        *reinterpret_cast<unsigned short*>(Bw + j * BSTR + k) = f2h(v);
    }

    const int orow = tid >> 4;
    const int oc   = tid & 15;
    const int hcol = ic * 16 + oc;
    const int brow = bg * 16 + orow;
    const float bh = bhn[hcol];
    float hold = h0[brow * HDIM + hcol];   // owner-thread register copy of h_old

    const int lrow = lane & 15;
    const int lkof = (lane >> 4) * 8;
    const uint32_t* hp = g_hp + bg * 16 * HDIM;   // group's 16 rows, packed fp16 hi/lo

    __syncthreads();

    for (int t = 0; t < T_STEPS; ++t) {
        // --- prefetch gi (read-once stream: evict-first) ---
        const float* gp = g_gi + ((size_t)t * BATCH + brow) * G3 + hcol;
        float gr = __ldcs(gp), gz = __ldcs(gp + 512), gn = __ldcs(gp + 1024);

        // --- per-warp unpack of this warp's A k-slice [ks*64, ks*64+64) ---
        {
            const uint32_t* hps = hp + ks * 64;
            #pragma unroll
            for (int i = lane; i < 256; i += 32) {
                int m   = i >> 4;
                int q16 = (i & 15) * 4;
                uint4 p = *(const uint4*)&hps[m * HDIM + q16];
                uint32_t hi01 = __byte_perm(p.x, p.y, 0x7632);
                uint32_t lo01 = __byte_perm(p.x, p.y, 0x5410);
                uint32_t hi23 = __byte_perm(p.z, p.w, 0x7632);
                uint32_t lo23 = __byte_perm(p.z, p.w, 0x5410);
                *(uint2*)(Ah + m * BSTR + ks * 64 + q16) = make_uint2(hi01, hi23);
                *(uint2*)(Al + m * BSTR + ks * 64 + q16) = make_uint2(lo01, lo23);
            }
        }
        __syncwarp();

        // --- fused GEMM: per ki load Ah/Al + Bw fragments once, 12 MMAs ---
        float acc[6][4];
        #pragma unroll
        for (int nt = 0; nt < 6; ++nt)
            #pragma unroll
            for (int i = 0; i < 4; ++i) acc[nt][i] = 0.f;

        #pragma unroll
        for (int ki = 0; ki < 4; ++ki) {
            const int k0 = ks * 64 + ki * 16;
            uint32_t ah[4], al[4];
            ldsm_x4(ah[0], ah[1], ah[2], ah[3], s2u(Ah + lrow * BSTR + k0 + lkof));
            ldsm_x4(al[0], al[1], al[2], al[3], s2u(Al + lrow * BSTR + k0 + lkof));
            uint32_t bwf[3][4];
            #pragma unroll
            for (int bt = 0; bt < 3; ++bt)
                ldsm_x4(bwf[bt][0], bwf[bt][1], bwf[bt][2], bwf[bt][3],
                        s2u(Bw + (bt * 16 + lrow) * BSTR + k0 + lkof));
            #pragma unroll
            for (int nt = 0; nt < 6; ++nt) {
                const int bt = nt >> 1, od = nt & 1;
                mma16816h(acc[nt], ah, bwf[bt][od], bwf[bt][od + 2]);
                mma16816h(acc[nt], al, bwf[bt][od], bwf[bt][od + 2]);
            }
        }

        // --- stage k-split partials ---
        {
            const int pr  = lane >> 2;
            const int pcb = (lane & 3) * 2;
            #pragma unroll
            for (int nt = 0; nt < 6; ++nt) {
                const int col = nt * 8 + pcb;
                *(float2*)&parts[(ks * 16 + pr) * 50 + col]     = make_float2(acc[nt][0], acc[nt][1]);
                *(float2*)&parts[(ks * 16 + pr + 8) * 50 + col] = make_float2(acc[nt][2], acc[nt][3]);
            }
        }
        __syncthreads();

        // --- reduce 8 k-splits + gates; publish h (fp16 hi/lo), then arrive ---
        float hnew;
        {
            float sr = 0.f, sz = 0.f, sn = 0.f;
            #pragma unroll
            for (int k2 = 0; k2 < 8; ++k2) {
                const float* q = &parts[(k2 * 16 + orow) * 50];
                sr += q[oc]; sz += q[16 + oc]; sn += q[32 + oc];
            }
            float er = __expf(-(gr + sr));
            float rr = __fdividef(1.f, 1.f + er);
            float ez = __expf(-(gz + sz));
            float zz = __fdividef(1.f, 1.f + ez);
            float e2 = __expf(2.f * (gn + rr * (sn + bh)));
            float nn = 1.f - __fdividef(2.f, e2 + 1.f);   // tanh, saturates safely
            hnew = (1.f - zz) * nn + zz * hold;
            hold = hnew;
            unsigned short hi = f2h(hnew);
            unsigned short lo = f2h(hnew - h2f(hi));
            g_hp[brow * HDIM + hcol] = ((uint32_t)hi << 16) | lo;
        }

        // --- CG-style group barrier on private 128B line; out-store (streaming)
        //     inside the wait window ---
        __syncthreads();
        if (tid == 0) red_release_gpu(bar, 1);
        __stcs(&out[((size_t)t * BATCH + brow) * HDIM + hcol], hnew);
        if (tid == 0) {
            const int target = (t + 1) * 32;
            while (ld_acquire_gpu(bar) < target) { }
        }
        __syncthreads();
    }
}

// ---------------- launch (serial single-stream, proven) ----------------
extern "C" void kernel_launch(void* const* d_in, const int* in_sizes, int n_in,
                              void* d_out, int out_size)
{
    const float* x   = (const float*)d_in[0];   // [T,B,D]
    const float* h0  = (const float*)d_in[1];   // [B,H]
    const float* Wi  = (const float*)d_in[2];   // [D,3H]
    const float* Wh  = (const float*)d_in[3];   // [H,3H]
    const float* bi  = (const float*)d_in[4];   // [3H]
    const float* bhn = (const float*)d_in[5];   // [H]
    float* out = (float*)d_out;                 // [T,B,H]
    (void)in_sizes; (void)n_in; (void)out_size;

    cudaFuncSetAttribute(gru_rec_kernel,
                         cudaFuncAttributeMaxDynamicSharedMemorySize, REC_SMEM_BYTES);

    gru_init_kernel<<<32, 1024>>>(h0);

    conv_x_kernel<<<(MROWS * DDIM / 4) / 256, 256>>>(x);
    conv_w_kernel<<<dim3(16, 48), dim3(32, 8)>>>(Wi);

    dim3 g1(G3 / 128, MROWS / 128);   // (12, 256)
    gi_mma_kernel<<<g1, 256>>>(bi);

    gru_rec_kernel<<<128, 256, REC_SMEM_BYTES>>>(h0, Wh, bhn, out);
}